// round 3
// baseline (speedup 1.0000x reference)
#include <cuda_runtime.h>
#include <cuda_bf16.h>

// ---------------------------------------------------------------------------
// FCOS head on GB300 — round 1: fp32 tiled direct conv baseline (infra retry,
// CIN_CHUNK widened to 16 to halve barrier/staging overhead).
// FPN: lat 1x1 -> (p5), up-add, 3x3 out convs; heads: 4x stem(3x3,relu) x2
// paths per level, finals (cls 80 / box 4 / ctr 1) written packed into d_out.
// ---------------------------------------------------------------------------

#define NUMC 80
#define CHTOT 85       // 80 cls + 4 box + 1 ctr
#define TOTLOC 5376    // 64*64 + 32*32 + 16*16
#define B 2
#define FPNC 256

// Scratch (device globals; allocation inside kernel_launch is forbidden)
__device__ float g_l3[B * FPNC * 64 * 64];
__device__ float g_l4[B * FPNC * 32 * 32];
__device__ float g_l5[B * FPNC * 16 * 16];
__device__ float g_p3[B * FPNC * 64 * 64];
__device__ float g_p4[B * FPNC * 32 * 32];
__device__ float g_p5[B * FPNC * 16 * 16];
__device__ float g_t0[B * FPNC * 64 * 64];
__device__ float g_t1[B * FPNC * 64 * 64];
__device__ float g_t2[B * FPNC * 64 * 64];
__device__ float g_t3[B * FPNC * 64 * 64];

// ---------------------------------------------------------------------------
// 3x3 conv, pad=1, stride=1. Block: 64 couts x (8x8 pixels), 256 threads,
// per-thread 4 couts x 4 pixels. K-loop over 16-cin chunks staged in smem.
// packed==1 writes out[(b*TOTLOC + loc_off + y*W + x)*85 + ch_off + co].
// ---------------------------------------------------------------------------
#define CIN_CHUNK 16

__global__ __launch_bounds__(256)
void conv3x3_k(const float* __restrict__ in, const float* __restrict__ wgt,
               const float* __restrict__ bias, float* __restrict__ out,
               int Cin, int Cout, int H, int W,
               int relu, int packed, int loc_off, int ch_off)
{
    __shared__ float  sIn[CIN_CHUNK][10][12];
    __shared__ float4 sW[CIN_CHUNK][9][16];

    const int tid = threadIdx.x;
    const int tilesX = W >> 3;
    const int tx0 = (blockIdx.x % tilesX) << 3;
    const int ty0 = (blockIdx.x / tilesX) << 3;
    const int coB = blockIdx.y * 64;
    const int b   = blockIdx.z;

    const int cg = tid >> 4;          // 0..15 -> 4 couts each
    const int pg = tid & 15;          // 0..15 -> 4 pixels each
    const int r  = pg >> 1;           // row in tile 0..7
    const int c4 = (pg & 1) << 2;     // col base 0 or 4
    const int co0 = coB + cg * 4;

    float acc[4][4];
#pragma unroll
    for (int i = 0; i < 4; i++)
#pragma unroll
        for (int j = 0; j < 4; j++) acc[i][j] = 0.f;

    const int HW = H * W;
    const float* inB = in + (long)b * Cin * HW;
    const bool compute = (co0 < Cout);
    const long cstride = (long)Cin * 9;

    for (int kc = 0; kc < Cin; kc += CIN_CHUNK) {
        __syncthreads();
        // input tile: 16 ci x 10 x 10 (zero-padded halo)
        for (int i = tid; i < CIN_CHUNK * 100; i += 256) {
            int ci  = i / 100;
            int rem = i - ci * 100;
            int iy  = rem / 10, ix = rem - iy * 10;
            int gy = ty0 - 1 + iy, gx = tx0 - 1 + ix;
            float v = 0.f;
            if ((unsigned)gy < (unsigned)H && (unsigned)gx < (unsigned)W)
                v = inB[(kc + ci) * HW + gy * W + gx];
            sIn[ci][iy][ix] = v;
        }
        // weights: 16 ci x 9 taps x 64 co, cout-contiguous float4
        for (int j = tid; j < CIN_CHUNK * 9 * 16; j += 256) {
            int cgg = j & 15;
            int tap = (j >> 4) % 9;
            int ci  = j / 144;
            int co  = coB + cgg * 4;
            float4 wv = make_float4(0.f, 0.f, 0.f, 0.f);
            const float* wp = wgt + ((long)co * Cin + (kc + ci)) * 9 + tap;
            if (co + 0 < Cout) wv.x = wp[0];
            if (co + 1 < Cout) wv.y = wp[cstride];
            if (co + 2 < Cout) wv.z = wp[2 * cstride];
            if (co + 3 < Cout) wv.w = wp[3 * cstride];
            sW[ci][tap][cgg] = wv;
        }
        __syncthreads();

        if (compute) {
#pragma unroll
            for (int ci = 0; ci < CIN_CHUNK; ci++) {
#pragma unroll
                for (int dy = 0; dy < 3; dy++) {
                    float rowv[6];
#pragma unroll
                    for (int j = 0; j < 6; j++)
                        rowv[j] = sIn[ci][r + dy][c4 + j];
#pragma unroll
                    for (int dx = 0; dx < 3; dx++) {
                        float4 wv = sW[ci][dy * 3 + dx][cg];
#pragma unroll
                        for (int p = 0; p < 4; p++) {
                            float xv = rowv[dx + p];
                            acc[0][p] += wv.x * xv;
                            acc[1][p] += wv.y * xv;
                            acc[2][p] += wv.z * xv;
                            acc[3][p] += wv.w * xv;
                        }
                    }
                }
            }
        }
    }

    if (!compute) return;
#pragma unroll
    for (int i = 0; i < 4; i++) {
        int co = co0 + i;
        if (co >= Cout) break;
        const float bv = bias[co];
        const int y = ty0 + r;
#pragma unroll
        for (int p = 0; p < 4; p++) {
            float v = acc[i][p] + bv;
            if (relu) v = fmaxf(v, 0.f);
            const int x = tx0 + c4 + p;
            if (!packed)
                out[(((long)b * Cout + co) * H + y) * W + x] = v;
            else
                out[((long)b * TOTLOC + loc_off + y * W + x) * CHTOT + ch_off + co] = v;
        }
    }
}

// ---------------------------------------------------------------------------
// Lateral 1x1 conv: Cout=256 fixed, thread computes 4 couts for one pixel.
// ---------------------------------------------------------------------------
__global__ __launch_bounds__(256)
void lat1x1_k(const float* __restrict__ in, const float* __restrict__ w,
              const float* __restrict__ bias, float* __restrict__ out,
              int Cin, int HW)
{
    int idx = blockIdx.x * 256 + threadIdx.x;
    int total = B * (FPNC / 4) * HW;
    if (idx >= total) return;
    int px = idx % HW;
    int t  = idx / HW;
    int cgr = t % (FPNC / 4);
    int b   = t / (FPNC / 4);
    int co = cgr * 4;
    float a0 = bias[co], a1 = bias[co + 1], a2 = bias[co + 2], a3 = bias[co + 3];
    const float* ip = in + (long)b * Cin * HW + px;
    const float* w0 = w + (long)(co + 0) * Cin;
    const float* w1 = w + (long)(co + 1) * Cin;
    const float* w2 = w + (long)(co + 2) * Cin;
    const float* w3 = w + (long)(co + 3) * Cin;
    for (int ci = 0; ci < Cin; ci++) {
        float v = ip[(long)ci * HW];
        a0 += w0[ci] * v; a1 += w1[ci] * v; a2 += w2[ci] * v; a3 += w3[ci] * v;
    }
    float* op = out + ((long)b * FPNC + co) * HW + px;
    op[0 * HW] = a0; op[1 * HW] = a1; op[2 * HW] = a2; op[3 * HW] = a3;
}

// ---------------------------------------------------------------------------
// dst[b,c,h,w] += src[b,c,h/2,w/2]  (nearest 2x upsample add)
// ---------------------------------------------------------------------------
__global__ __launch_bounds__(256)
void upadd_k(float* __restrict__ dst, const float* __restrict__ src, int H, int W)
{
    long idx = (long)blockIdx.x * 256 + threadIdx.x;
    long total = (long)B * FPNC * H * W;
    if (idx >= total) return;
    int x = idx % W;
    int y = (idx / W) % H;
    long bc = idx / ((long)H * W);
    dst[idx] += src[(bc * (H / 2) + (y >> 1)) * (W / 2) + (x >> 1)];
}

// ---------------------------------------------------------------------------
// Host-side launch plumbing
// ---------------------------------------------------------------------------
static void launch_conv(const float* in, const float* w, const float* bias, float* out,
                        int Cin, int Cout, int H, int W,
                        int relu, int packed, int loc_off, int ch_off)
{
    dim3 g((W / 8) * (H / 8), (Cout + 63) / 64, B);
    conv3x3_k<<<g, 256>>>(in, w, bias, out, Cin, Cout, H, W, relu, packed, loc_off, ch_off);
}

extern "C" void kernel_launch(void* const* d_in, const int* in_sizes, int n_in,
                              void* d_out, int out_size)
{
    // Resolve inputs by element count (robust to metadata ordering; biases
    // immediately follow their weight in every plausible order).
    auto idxOf = [&](int sz, int ord) -> int {
        int c = 0;
        for (int i = 0; i < n_in; i++)
            if (in_sizes[i] == sz) { if (c == ord) return i; c++; }
        return -1;
    };
    const int i_c3  = idxOf(2 * 64 * 64 * 64, 0);
    const int i_c4  = idxOf(2 * 160 * 32 * 32, 0);
    const int i_c5  = idxOf(2 * 400 * 16 * 16, 0);
    const int i_l3w = idxOf(256 * 64, 0);
    const int i_l4w = idxOf(256 * 160, 0);
    const int i_l5w = idxOf(256 * 400, 0);
    const int i_o3w = idxOf(256 * 256 * 9, 0);
    const int i_o4w = idxOf(256 * 256 * 9, 1);
    const int i_o5w = idxOf(256 * 256 * 9, 2);
    const int i_scw = idxOf(4 * 256 * 256 * 9, 0);
    const int i_sbw = idxOf(4 * 256 * 256 * 9, 1);
    const int i_cw  = idxOf(80 * 256 * 9, 0);
    const int i_bw  = idxOf(4 * 256 * 9, 0);
    const int i_tw  = idxOf(1 * 256 * 9, 0);

    const float* c3 = (const float*)d_in[i_c3];
    const float* c4 = (const float*)d_in[i_c4];
    const float* c5 = (const float*)d_in[i_c5];
    const float* l3w = (const float*)d_in[i_l3w]; const float* l3b = (const float*)d_in[i_l3w + 1];
    const float* l4w = (const float*)d_in[i_l4w]; const float* l4b = (const float*)d_in[i_l4w + 1];
    const float* l5w = (const float*)d_in[i_l5w]; const float* l5b = (const float*)d_in[i_l5w + 1];
    const float* o3w = (const float*)d_in[i_o3w]; const float* o3b = (const float*)d_in[i_o3w + 1];
    const float* o4w = (const float*)d_in[i_o4w]; const float* o4b = (const float*)d_in[i_o4w + 1];
    const float* o5w = (const float*)d_in[i_o5w]; const float* o5b = (const float*)d_in[i_o5w + 1];
    const float* scw = (const float*)d_in[i_scw]; const float* scb = (const float*)d_in[i_scw + 1];
    const float* sbw = (const float*)d_in[i_sbw]; const float* sbb = (const float*)d_in[i_sbw + 1];
    const float* cw  = (const float*)d_in[i_cw];  const float* cb  = (const float*)d_in[i_cw + 1];
    const float* bw  = (const float*)d_in[i_bw];  const float* bb  = (const float*)d_in[i_bw + 1];
    const float* tw  = (const float*)d_in[i_tw];  const float* tb  = (const float*)d_in[i_tw + 1];

    float *l3, *l4, *l5, *p3, *p4, *p5, *t0, *t1, *t2, *t3;
    cudaGetSymbolAddress((void**)&l3, g_l3);
    cudaGetSymbolAddress((void**)&l4, g_l4);
    cudaGetSymbolAddress((void**)&l5, g_l5);
    cudaGetSymbolAddress((void**)&p3, g_p3);
    cudaGetSymbolAddress((void**)&p4, g_p4);
    cudaGetSymbolAddress((void**)&p5, g_p5);
    cudaGetSymbolAddress((void**)&t0, g_t0);
    cudaGetSymbolAddress((void**)&t1, g_t1);
    cudaGetSymbolAddress((void**)&t2, g_t2);
    cudaGetSymbolAddress((void**)&t3, g_t3);

    float* out = (float*)d_out;

    // ---- FPN ----
    {
        int tot5 = B * (FPNC / 4) * 256;   // 16x16
        lat1x1_k<<<(tot5 + 255) / 256, 256>>>(c5, l5w, l5b, l5, 400, 256);
        int tot4 = B * (FPNC / 4) * 1024;  // 32x32
        lat1x1_k<<<(tot4 + 255) / 256, 256>>>(c4, l4w, l4b, l4, 160, 1024);
        int tot3 = B * (FPNC / 4) * 4096;  // 64x64
        lat1x1_k<<<(tot3 + 255) / 256, 256>>>(c3, l3w, l3b, l3, 64, 4096);
    }
    launch_conv(l5, o5w, o5b, p5, 256, 256, 16, 16, 0, 0, 0, 0);
    {
        long n4 = (long)B * FPNC * 32 * 32;
        upadd_k<<<(int)((n4 + 255) / 256), 256>>>(l4, l5, 32, 32);
    }
    launch_conv(l4, o4w, o4b, p4, 256, 256, 32, 32, 0, 0, 0, 0);
    {
        long n3 = (long)B * FPNC * 64 * 64;
        upadd_k<<<(int)((n3 + 255) / 256), 256>>>(l3, l4, 64, 64);
    }
    launch_conv(l3, o3w, o3b, p3, 256, 256, 64, 64, 0, 0, 0, 0);

    // ---- Heads ----
    struct Lvl { const float* p; int H, W, loc; };
    Lvl lv[3] = { { p3, 64, 64, 0 }, { p4, 32, 32, 4096 }, { p5, 16, 16, 5120 } };
    const long WSZ = 256L * 256 * 9;

    for (int L = 0; L < 3; L++) {
        const float* src;
        // cls stem: p -> t0 -> t1 -> t0 -> t1
        src = lv[L].p;
        for (int i = 0; i < 4; i++) {
            float* dst = (i & 1) ? t1 : t0;
            launch_conv(src, scw + i * WSZ, scb + i * 256, dst,
                        256, 256, lv[L].H, lv[L].W, 1, 0, 0, 0);
            src = dst;
        }
        launch_conv(src, cw, cb, out, 256, NUMC, lv[L].H, lv[L].W, 0, 1, lv[L].loc, 0);

        // box stem: p -> t2 -> t3 -> t2 -> t3
        src = lv[L].p;
        for (int i = 0; i < 4; i++) {
            float* dst = (i & 1) ? t3 : t2;
            launch_conv(src, sbw + i * WSZ, sbb + i * 256, dst,
                        256, 256, lv[L].H, lv[L].W, 1, 0, 0, 0);
            src = dst;
        }
        launch_conv(src, bw, bb, out, 256, 4, lv[L].H, lv[L].W, 0, 1, lv[L].loc, 80);
        launch_conv(src, tw, tb, out, 256, 1, lv[L].H, lv[L].W, 0, 1, lv[L].loc, 84);
    }
    (void)out_size;
}

// round 6
// speedup vs baseline: 1.1376x; 1.1376x over previous
#include <cuda_runtime.h>
#include <cuda_bf16.h>

// ---------------------------------------------------------------------------
// FCOS head on GB300 — round 4: tf32 mma.sync implicit-GEMM convs, NHWC padded
// activations, weights pre-transformed to [tap][ci][co].
// ---------------------------------------------------------------------------

#define NUMC 80
#define CHTOT 85
#define TOTLOC 5376
#define B 2

// padded NHWC activation scratch
__device__ float g_lat3[2 * 66 * 66 * 256];
__device__ float g_p3  [2 * 66 * 66 * 256];
__device__ float g_tA3 [2 * 66 * 66 * 256];
__device__ float g_tB3 [2 * 66 * 66 * 256];
__device__ float g_lat4[2 * 34 * 34 * 256];
__device__ float g_p4  [2 * 34 * 34 * 256];
__device__ float g_tA4 [2 * 34 * 34 * 256];
__device__ float g_tB4 [2 * 34 * 34 * 256];
__device__ float g_lat5[2 * 18 * 18 * 256];
__device__ float g_p5  [2 * 18 * 18 * 256];
__device__ float g_tA5 [2 * 18 * 18 * 256];
__device__ float g_tB5 [2 * 18 * 18 * 256];

// transformed weights [tap][ci][co], tf32-rounded
#define WSZ (256 * 256 * 9)
__device__ float g_wt[11 * WSZ];          // 0..2: out3/4/5; 3..6: stem_cls; 7..10: stem_box
__device__ float g_wt_cls[9 * 256 * 80];
__device__ float g_wt_bc [9 * 256 * 5];
__device__ float g_bias_bc[5];

__device__ __forceinline__ float tf32r(float x) {
    float r;
    asm("cvt.rna.tf32.f32 %0, %1;" : "=f"(r) : "f"(x));
    return r;
}

__device__ __forceinline__ void mma8(float4& d, float2 a02, float2 a13, float2 b) {
    asm volatile(
        "mma.sync.aligned.m16n8k8.row.col.f32.tf32.tf32.f32 "
        "{%0,%1,%2,%3}, {%4,%5,%6,%7}, {%8,%9}, {%0,%1,%2,%3};\n"
        : "+f"(d.x), "+f"(d.y), "+f"(d.z), "+f"(d.w)
        : "r"(__float_as_uint(a02.x)), "r"(__float_as_uint(a13.x)),
          "r"(__float_as_uint(a02.y)), "r"(__float_as_uint(a13.y)),
          "r"(__float_as_uint(b.x)),   "r"(__float_as_uint(b.y)));
}

// ---------------------------------------------------------------------------
// Tensor-core 3x3 conv, pad=1, Cin=256 fixed. Input NHWC padded (H+2,W+2,256).
// CTA: M=128 pixels (8 rows x 16 cols) x N=128 couts. 8 warps = 4m x 2n.
// packed==0: NHWC padded out (tf32-rounded, optional relu)
// packed==1: out[(b*TOTLOC + loc + y*W + x)*85 + ch_off + co], fp32
// ---------------------------------------------------------------------------
#define SIN_F (10 * 18 * 12)
#define SW_F  (9 * 128 * 10)
#define SMEM_BYTES ((SIN_F + SW_F) * 4)

__global__ __launch_bounds__(256)
void conv_tc_k(const float* __restrict__ in, const float* __restrict__ wT,
               const float* __restrict__ bias, float* __restrict__ out,
               int H, int W, int Cout, int relu, int packed, int loc_off, int ch_off)
{
    extern __shared__ float sm[];
    float* sIn = sm;            // [10][18][12] (k-slot perm, padded)
    float* sW  = sm + SIN_F;    // [9][128][10] (k-slot perm, padded)

    const int tid = threadIdx.x, lane = tid & 31, wrp = tid >> 5;
    const int mw = wrp >> 1, nw = wrp & 1, gID = lane >> 2, tq = lane & 3;
    const int tilesX = W >> 4;
    const int x0 = (blockIdx.x % tilesX) << 4;
    const int y0 = (blockIdx.x / tilesX) << 3;
    const int coB = blockIdx.y << 7;
    const int b = blockIdx.z;
    const int HP = H + 2, WP = W + 2;

    float4 acc[2][8];
#pragma unroll
    for (int s = 0; s < 2; s++)
#pragma unroll
        for (int nt = 0; nt < 8; nt++) acc[s][nt] = make_float4(0.f, 0.f, 0.f, 0.f);

    const float* inB = in + (long)b * HP * WP * 256;

    for (int kc = 0; kc < 256; kc += 8) {
        __syncthreads();
        // halo: 10 rows x 18 cols x 8 cin
        for (int i = tid; i < 1440; i += 256) {
            int k  = i & 7;
            int cl = (i >> 3) % 18;
            int rw = (i >> 3) / 18;
            float v = inB[((long)(y0 + rw) * WP + (x0 + cl)) * 256 + kc + k];
            sIn[(rw * 18 + cl) * 12 + ((k & 3) << 1) + (k >> 2)] = v;
        }
        // weights: 9 taps x 8 k x 128 n (n innermost -> coalesced)
        for (int i = tid; i < 9216; i += 256) {
            int n   = i & 127;
            int k   = (i >> 7) & 7;
            int tap = i >> 10;
            int co  = coB + n;
            float v = (co < Cout) ? wT[((long)(tap * 256 + kc + k)) * Cout + co] : 0.f;
            sW[(tap * 128 + n) * 10 + ((k & 3) << 1) + (k >> 2)] = v;
        }
        __syncthreads();

#pragma unroll
        for (int tap = 0; tap < 9; tap++) {
            const int dy = tap / 3, dx = tap - 3 * (tap / 3);
            const float* pr0 = &sIn[((2 * mw + dy) * 18 + (gID + dx)) * 12 + (tq << 1)];
            float2 a02_0 = *(const float2*)pr0;
            float2 a13_0 = *(const float2*)(pr0 + 8 * 12);
            float2 a02_1 = *(const float2*)(pr0 + 18 * 12);
            float2 a13_1 = *(const float2*)(pr0 + 18 * 12 + 8 * 12);
#pragma unroll
            for (int nt = 0; nt < 8; nt++) {
                float2 bb = *(const float2*)&sW[(tap * 128 + nw * 64 + nt * 8 + gID) * 10 + (tq << 1)];
                mma8(acc[0][nt], a02_0, a13_0, bb);
                mma8(acc[1][nt], a02_1, a13_1, bb);
            }
        }
    }

    // epilogue
    if (!packed) {
        float* ob = out + (long)b * HP * WP * 256;
#pragma unroll
        for (int s = 0; s < 2; s++) {
            int y = y0 + 2 * mw + s;
            long rowb = (long)(y + 1) * WP * 256;
#pragma unroll
            for (int nt = 0; nt < 8; nt++) {
                int co = coB + nw * 64 + nt * 8 + (tq << 1);
                float b0 = bias[co], b1 = bias[co + 1];
                float4 a = acc[s][nt];
                float v0 = a.x + b0, v1 = a.y + b1, v2 = a.z + b0, v3 = a.w + b1;
                if (relu) {
                    v0 = fmaxf(v0, 0.f); v1 = fmaxf(v1, 0.f);
                    v2 = fmaxf(v2, 0.f); v3 = fmaxf(v3, 0.f);
                }
                float2* p0 = (float2*)&ob[rowb + (long)(x0 + gID + 1) * 256 + co];
                *p0 = make_float2(tf32r(v0), tf32r(v1));
                float2* p1 = (float2*)&ob[rowb + (long)(x0 + gID + 9) * 256 + co];
                *p1 = make_float2(tf32r(v2), tf32r(v3));
            }
        }
    } else {
#pragma unroll
        for (int s = 0; s < 2; s++) {
            int y = y0 + 2 * mw + s;
            long base  = ((long)b * TOTLOC + loc_off + (long)y * W + x0 + gID) * CHTOT + ch_off;
            long base8 = base + 8L * CHTOT;
#pragma unroll
            for (int nt = 0; nt < 8; nt++) {
                int co = coB + nw * 64 + nt * 8 + (tq << 1);
                if (co < Cout) {
                    float bv = bias[co];
                    float4 a = acc[s][nt];
                    out[base  + co] = a.x + bv;
                    out[base8 + co] = a.z + bv;
                    if (co + 1 < Cout) {
                        float bv1 = bias[co + 1];
                        out[base  + co + 1] = a.y + bv1;
                        out[base8 + co + 1] = a.w + bv1;
                    }
                }
            }
        }
    }
}

// ---------------------------------------------------------------------------
// lateral 1x1: NCHW fp32 in -> NHWC padded tf32 out (4 couts/thread)
// ---------------------------------------------------------------------------
__global__ __launch_bounds__(256)
void lat_k(const float* __restrict__ in, const float* __restrict__ w,
           const float* __restrict__ bias, float* __restrict__ out,
           int Cin, int H, int W)
{
    int HW = H * W;
    int idx = blockIdx.x * 256 + threadIdx.x;
    int total = B * 64 * HW;
    if (idx >= total) return;
    int px = idx % HW;
    int t  = idx / HW;
    int cg = t % 64;
    int b  = t / 64;
    int co = cg * 4;
    float a0 = bias[co], a1 = bias[co + 1], a2 = bias[co + 2], a3 = bias[co + 3];
    const float* ip = in + (long)b * Cin * HW + px;
    const float* w0 = w + (long)(co + 0) * Cin;
    const float* w1 = w + (long)(co + 1) * Cin;
    const float* w2 = w + (long)(co + 2) * Cin;
    const float* w3 = w + (long)(co + 3) * Cin;
    for (int ci = 0; ci < Cin; ci++) {
        float v = ip[(long)ci * HW];
        a0 += w0[ci] * v; a1 += w1[ci] * v; a2 += w2[ci] * v; a3 += w3[ci] * v;
    }
    int y = px / W, x = px % W;
    float4* op = (float4*)&out[((long)(b * (H + 2) + y + 1) * (W + 2) + x + 1) * 256 + co];
    *op = make_float4(tf32r(a0), tf32r(a1), tf32r(a2), tf32r(a3));
}

// dst(H,W padded NHWC) += nearest-up2(src(H/2,W/2 padded NHWC)); tf32 re-round
__global__ __launch_bounds__(256)
void upadd_k(float* __restrict__ dst, const float* __restrict__ src, int H, int W)
{
    long idx = (long)blockIdx.x * 256 + threadIdx.x;
    long total = (long)B * H * W * 64;
    if (idx >= total) return;
    int c4 = idx & 63;
    long p = idx >> 6;
    int x = p % W;
    int y = (p / W) % H;
    int b = p / ((long)W * H);
    float4* d = (float4*)&dst[((long)(b * (H + 2) + y + 1) * (W + 2) + x + 1) * 256 + c4 * 4];
    const float4* s = (const float4*)&src[((long)(b * (H / 2 + 2) + (y >> 1) + 1) * (W / 2 + 2) + (x >> 1) + 1) * 256 + c4 * 4];
    float4 dv = *d, sv = *s;
    *d = make_float4(tf32r(dv.x + sv.x), tf32r(dv.y + sv.y),
                     tf32r(dv.z + sv.z), tf32r(dv.w + sv.w));
}

__global__ void zero_k(float4* p, long n4)
{
    long i = (long)blockIdx.x * blockDim.x + threadIdx.x;
    long stride = (long)gridDim.x * blockDim.x;
    for (; i < n4; i += stride) p[i] = make_float4(0.f, 0.f, 0.f, 0.f);
}

// OIHW [CoutSrc][256][9] -> [tap][ci][CoutDst] at column offset coOff, tf32
__global__ void transform_k(const float* __restrict__ src, float* __restrict__ dst,
                            int CoutSrc, int CoutDst, int coOff)
{
    long idx = (long)blockIdx.x * blockDim.x + threadIdx.x;
    long total = 9L * 256 * CoutSrc;
    if (idx >= total) return;
    int co = idx % CoutSrc;
    long r = idx / CoutSrc;
    int ci = r % 256;
    int tap = r / 256;
    dst[((long)(tap * 256 + ci)) * CoutDst + coOff + co] =
        tf32r(src[(long)co * 2304 + ci * 9 + tap]);
}

__global__ void biasbc_k(const float* bb, const float* tb, float* dst)
{
    int i = threadIdx.x;
    if (i < 4) dst[i] = bb[i];
    else if (i == 4) dst[i] = tb[0];
}

// ---------------------------------------------------------------------------
static void conv_tc(const float* in, const float* wT, const float* bias, float* out,
                    int H, int W, int Cout, int relu, int packed, int loc, int choff)
{
    dim3 g((W / 16) * (H / 8), (Cout + 127) / 128, B);
    conv_tc_k<<<g, 256, SMEM_BYTES>>>(in, wT, bias, out, H, W, Cout, relu, packed, loc, choff);
}

extern "C" void kernel_launch(void* const* d_in, const int* in_sizes, int n_in,
                              void* d_out, int out_size)
{
    auto idxOf = [&](int sz, int ord) -> int {
        int c = 0;
        for (int i = 0; i < n_in; i++)
            if (in_sizes[i] == sz) { if (c == ord) return i; c++; }
        return -1;
    };
    const int i_c3  = idxOf(2 * 64 * 64 * 64, 0);
    const int i_c4  = idxOf(2 * 160 * 32 * 32, 0);
    const int i_c5  = idxOf(2 * 400 * 16 * 16, 0);
    const int i_l3w = idxOf(256 * 64, 0);
    const int i_l4w = idxOf(256 * 160, 0);
    const int i_l5w = idxOf(256 * 400, 0);
    const int i_o3w = idxOf(256 * 256 * 9, 0);
    const int i_o4w = idxOf(256 * 256 * 9, 1);
    const int i_o5w = idxOf(256 * 256 * 9, 2);
    const int i_scw = idxOf(4 * 256 * 256 * 9, 0);
    const int i_sbw = idxOf(4 * 256 * 256 * 9, 1);
    const int i_cw  = idxOf(80 * 256 * 9, 0);
    const int i_bw  = idxOf(4 * 256 * 9, 0);
    const int i_tw  = idxOf(1 * 256 * 9, 0);

    const float* c3 = (const float*)d_in[i_c3];
    const float* c4 = (const float*)d_in[i_c4];
    const float* c5 = (const float*)d_in[i_c5];
    const float* l3w = (const float*)d_in[i_l3w]; const float* l3b = (const float*)d_in[i_l3w + 1];
    const float* l4w = (const float*)d_in[i_l4w]; const float* l4b = (const float*)d_in[i_l4w + 1];
    const float* l5w = (const float*)d_in[i_l5w]; const float* l5b = (const float*)d_in[i_l5w + 1];
    const float* o3w = (const float*)d_in[i_o3w]; const float* o3b = (const float*)d_in[i_o3w + 1];
    const float* o4w = (const float*)d_in[i_o4w]; const float* o4b = (const float*)d_in[i_o4w + 1];
    const float* o5w = (const float*)d_in[i_o5w]; const float* o5b = (const float*)d_in[i_o5w + 1];
    const float* scw = (const float*)d_in[i_scw]; const float* scb = (const float*)d_in[i_scw + 1];
    const float* sbw = (const float*)d_in[i_sbw]; const float* sbb = (const float*)d_in[i_sbw + 1];
    const float* cw  = (const float*)d_in[i_cw];  const float* cb  = (const float*)d_in[i_cw + 1];
    const float* bw  = (const float*)d_in[i_bw];  const float* bb  = (const float*)d_in[i_bw + 1];
    const float* tw  = (const float*)d_in[i_tw];  const float* tb  = (const float*)d_in[i_tw + 1];

    float *lat3, *lat4, *lat5, *p3, *p4, *p5, *tA3, *tB3, *tA4, *tB4, *tA5, *tB5;
    float *wt, *wt_cls, *wt_bc, *bias_bc;
    cudaGetSymbolAddress((void**)&lat3, g_lat3); cudaGetSymbolAddress((void**)&lat4, g_lat4);
    cudaGetSymbolAddress((void**)&lat5, g_lat5); cudaGetSymbolAddress((void**)&p3, g_p3);
    cudaGetSymbolAddress((void**)&p4, g_p4);     cudaGetSymbolAddress((void**)&p5, g_p5);
    cudaGetSymbolAddress((void**)&tA3, g_tA3);   cudaGetSymbolAddress((void**)&tB3, g_tB3);
    cudaGetSymbolAddress((void**)&tA4, g_tA4);   cudaGetSymbolAddress((void**)&tB4, g_tB4);
    cudaGetSymbolAddress((void**)&tA5, g_tA5);   cudaGetSymbolAddress((void**)&tB5, g_tB5);
    cudaGetSymbolAddress((void**)&wt, g_wt);     cudaGetSymbolAddress((void**)&wt_cls, g_wt_cls);
    cudaGetSymbolAddress((void**)&wt_bc, g_wt_bc); cudaGetSymbolAddress((void**)&bias_bc, g_bias_bc);

    cudaFuncSetAttribute(conv_tc_k, cudaFuncAttributeMaxDynamicSharedMemorySize, SMEM_BYTES);

    float* out = (float*)d_out;

    // ---- zero padded activation buffers (borders must be 0) ----
    {
        long n3 = 2L * 66 * 66 * 64, n4 = 2L * 34 * 34 * 64, n5 = 2L * 18 * 18 * 64;
        zero_k<<<512, 256>>>((float4*)lat3, n3); zero_k<<<512, 256>>>((float4*)p3, n3);
        zero_k<<<512, 256>>>((float4*)tA3, n3);  zero_k<<<512, 256>>>((float4*)tB3, n3);
        zero_k<<<256, 256>>>((float4*)lat4, n4); zero_k<<<256, 256>>>((float4*)p4, n4);
        zero_k<<<256, 256>>>((float4*)tA4, n4);  zero_k<<<256, 256>>>((float4*)tB4, n4);
        zero_k<<<128, 256>>>((float4*)lat5, n5); zero_k<<<128, 256>>>((float4*)p5, n5);
        zero_k<<<128, 256>>>((float4*)tA5, n5);  zero_k<<<128, 256>>>((float4*)tB5, n5);
    }

    // ---- weight transforms ----
    {
        long tot = 9L * 256 * 256;
        int gb = (int)((tot + 255) / 256);
        transform_k<<<gb, 256>>>(o3w, wt + 0 * WSZ, 256, 256, 0);
        transform_k<<<gb, 256>>>(o4w, wt + 1 * WSZ, 256, 256, 0);
        transform_k<<<gb, 256>>>(o5w, wt + 2 * WSZ, 256, 256, 0);
        for (int i = 0; i < 4; i++) {
            transform_k<<<gb, 256>>>(scw + (long)i * WSZ, wt + (3 + i) * (long)WSZ, 256, 256, 0);
            transform_k<<<gb, 256>>>(sbw + (long)i * WSZ, wt + (7 + i) * (long)WSZ, 256, 256, 0);
        }
        long totc = 9L * 256 * 80;
        transform_k<<<(int)((totc + 255) / 256), 256>>>(cw, wt_cls, 80, 80, 0);
        long totb = 9L * 256 * 4;
        transform_k<<<(int)((totb + 255) / 256), 256>>>(bw, wt_bc, 4, 5, 0);
        long tott = 9L * 256 * 1;
        transform_k<<<(int)((tott + 255) / 256), 256>>>(tw, wt_bc, 1, 5, 4);
        biasbc_k<<<1, 8>>>(bb, tb, bias_bc);
    }

    // ---- FPN ----
    lat_k<<<(B * 64 * 256 + 255) / 256, 256>>>(c5, l5w, l5b, lat5, 400, 16, 16);
    lat_k<<<(B * 64 * 1024 + 255) / 256, 256>>>(c4, l4w, l4b, lat4, 160, 32, 32);
    lat_k<<<(B * 64 * 4096 + 255) / 256, 256>>>(c3, l3w, l3b, lat3, 64, 64, 64);

    conv_tc(lat5, wt + 2 * (long)WSZ, o5b, p5, 16, 16, 256, 0, 0, 0, 0);
    {
        long n = (long)B * 32 * 32 * 64;
        upadd_k<<<(int)((n + 255) / 256), 256>>>(lat4, lat5, 32, 32);
    }
    conv_tc(lat4, wt + 1 * (long)WSZ, o4b, p4, 32, 32, 256, 0, 0, 0, 0);
    {
        long n = (long)B * 64 * 64 * 64;
        upadd_k<<<(int)((n + 255) / 256), 256>>>(lat3, lat4, 64, 64);
    }
    conv_tc(lat3, wt + 0 * (long)WSZ, o3b, p3, 64, 64, 256, 0, 0, 0, 0);

    // ---- heads ----
    struct Lvl { float *p, *tA, *tB; int H, W, loc; };
    Lvl lv[3] = { { p3, tA3, tB3, 64, 64, 0 },
                  { p4, tA4, tB4, 32, 32, 4096 },
                  { p5, tA5, tB5, 16, 16, 5120 } };

    for (int L = 0; L < 3; L++) {
        const float* src = lv[L].p;
        for (int i = 0; i < 4; i++) {
            float* dst = (i & 1) ? lv[L].tB : lv[L].tA;
            conv_tc(src, wt + (3 + i) * (long)WSZ, scb + i * 256, dst,
                    lv[L].H, lv[L].W, 256, 1, 0, 0, 0);
            src = dst;
        }
        conv_tc(src, wt_cls, cb, out, lv[L].H, lv[L].W, NUMC, 0, 1, lv[L].loc, 0);

        src = lv[L].p;
        for (int i = 0; i < 4; i++) {
            float* dst = (i & 1) ? lv[L].tB : lv[L].tA;
            conv_tc(src, wt + (7 + i) * (long)WSZ, sbb + i * 256, dst,
                    lv[L].H, lv[L].W, 256, 1, 0, 0, 0);
            src = dst;
        }
        conv_tc(src, wt_bc, bias_bc, out, lv[L].H, lv[L].W, 5, 0, 1, lv[L].loc, 80);
    }
    (void)out_size;
}

// round 7
// speedup vs baseline: 2.7223x; 2.3929x over previous
#include <cuda_runtime.h>
#include <cuda_bf16.h>

// ---------------------------------------------------------------------------
// FCOS head on GB300 — round 7: bf16 m16n8k16 mma.sync implicit-GEMM convs.
// Activations/weights in global bf16, pre-permuted into MMA word order, staged
// with cp.async 16B copies, double-buffered smem.
// ---------------------------------------------------------------------------

#define NUMC 80
#define CHTOT 85
#define TOTLOC 5376
#define B 2

// padded NHWC bf16 activation scratch (u32 = bf16x2 words, 128 words/pixel)
__device__ unsigned g_lat3[2 * 66 * 66 * 128];
__device__ unsigned g_p3  [2 * 66 * 66 * 128];
__device__ unsigned g_tA3 [2 * 66 * 66 * 128];
__device__ unsigned g_tB3 [2 * 66 * 66 * 128];
__device__ unsigned g_lat4[2 * 34 * 34 * 128];
__device__ unsigned g_p4  [2 * 34 * 34 * 128];
__device__ unsigned g_tA4 [2 * 34 * 34 * 128];
__device__ unsigned g_tB4 [2 * 34 * 34 * 128];
__device__ unsigned g_lat5[2 * 18 * 18 * 128];
__device__ unsigned g_p5  [2 * 18 * 18 * 128];
__device__ unsigned g_tA5 [2 * 18 * 18 * 128];
__device__ unsigned g_tB5 [2 * 18 * 18 * 128];

// transformed bf16 weights: [group16][tap9][coutPad][8 words], slot-permuted
#define W256 (16 * 9 * 256 * 8)          // u32 words per 256-cout conv
#define W128 (16 * 9 * 128 * 8)
__device__ unsigned g_wt[11 * W256];     // 0..2 out3/4/5, 3..6 stem_cls, 7..10 stem_box
__device__ unsigned g_wt_cls[W128];      // cls, couts padded to 128 (pre-zeroed)
__device__ unsigned g_wt_bc [W128];      // box(4)+ctr(1) at coOff 0/4, padded 128
__device__ float    g_bias_bc[5];

__device__ __forceinline__ unsigned pk(float a, float b) {
    __nv_bfloat162 h = __floats2bfloat162_rn(a, b);
    return *(unsigned*)&h;
}
__device__ __forceinline__ int slot_of(int w) { return ((w & 3) << 1) | (w >> 2); }

__device__ __forceinline__ void cpa16(void* smem, const void* g) {
    unsigned s = (unsigned)__cvta_generic_to_shared(smem);
    asm volatile("cp.async.cg.shared.global [%0], [%1], 16;" :: "r"(s), "l"(g) : "memory");
}

__device__ __forceinline__ void mma16(float4& d, uint2 A0, uint2 A1, uint2 Bv) {
    asm volatile(
        "mma.sync.aligned.m16n8k16.row.col.f32.bf16.bf16.f32 "
        "{%0,%1,%2,%3}, {%4,%5,%6,%7}, {%8,%9}, {%0,%1,%2,%3};\n"
        : "+f"(d.x), "+f"(d.y), "+f"(d.z), "+f"(d.w)
        : "r"(A0.x), "r"(A1.x), "r"(A0.y), "r"(A1.y),
          "r"(Bv.x), "r"(Bv.y));
}

// ---------------------------------------------------------------------------
// bf16 tensor-core 3x3 conv, pad=1, Cin=256. Input padded NHWC bf16 words.
// CTA: 128 pixels (8 rows x 16 cols) x 128 couts; 8 warps = 4m x 2n.
// 16 K-chunks of 16 cin, cp.async double-buffered.
// ---------------------------------------------------------------------------
#define SIN_W (180 * 12)                 // 10x18 pixels, 12-word stride
#define SW_W  (9 * 128 * 12)             // taps x n, 12-word stride
#define BUF_W (SIN_W + SW_W)
#define SMEM_BYTES (2 * BUF_W * 4)

__global__ __launch_bounds__(256)
void conv_tc_k(const unsigned* __restrict__ in, const unsigned* __restrict__ wgt,
               const float* __restrict__ bias, void* __restrict__ outv,
               int H, int W, int Cout, int CoutPad,
               int relu, int packed, int loc_off, int ch_off)
{
    extern __shared__ unsigned sm[];

    const int tid = threadIdx.x, lane = tid & 31, wrp = tid >> 5;
    const int mw = wrp >> 1, nw = wrp & 1, gID = lane >> 2, tq = lane & 3;
    const int tilesX = W >> 4;
    const int x0 = (blockIdx.x % tilesX) << 4;
    const int y0 = (blockIdx.x / tilesX) << 3;
    const int coB = blockIdx.y << 7;
    const int b = blockIdx.z;
    const int HP = H + 2, WP = W + 2;

    const unsigned* inB = in + (long)b * HP * WP * 128;

    float4 acc[2][8];
#pragma unroll
    for (int s = 0; s < 2; s++)
#pragma unroll
        for (int nt = 0; nt < 8; nt++) acc[s][nt] = make_float4(0.f, 0.f, 0.f, 0.f);

    // stage chunk g into buffer buf
    auto stage = [&](int g, int buf) {
        unsigned* sIn = sm + buf * BUF_W;
        unsigned* sW  = sIn + SIN_W;
        // input halo: 180 pixels x 8 words (two 16B halves)
        for (int i = tid; i < 360; i += 256) {
            int pix = i >> 1, half = i & 1;
            int rw = pix / 18, cl = pix - rw * 18;
            const unsigned* src = inB + ((long)(y0 + rw) * WP + (x0 + cl)) * 128 + g * 8 + half * 4;
            cpa16(&sIn[pix * 12 + half * 4], src);
        }
        // weights: 9 taps x 128 n x 8 words (two halves)
        for (int i = tid; i < 2304; i += 256) {
            int half = i & 1;
            int n    = (i >> 1) & 127;
            int tap  = i >> 8;
            const unsigned* src = wgt + (((long)(g * 9 + tap) * CoutPad) + coB + n) * 8 + half * 4;
            cpa16(&sW[(tap * 128 + n) * 12 + half * 4], src);
        }
        asm volatile("cp.async.commit_group;" ::: "memory");
    };

    stage(0, 0);
    stage(1, 1);

    for (int c = 0; c < 16; c++) {
        if (c < 15) asm volatile("cp.async.wait_group 1;" ::: "memory");
        else        asm volatile("cp.async.wait_group 0;" ::: "memory");
        __syncthreads();

        const unsigned* sIn = sm + (c & 1) * BUF_W;
        const unsigned* sW  = sIn + SIN_W;

#pragma unroll
        for (int tap = 0; tap < 9; tap++) {
            const int dy = tap / 3, dx = tap - 3 * (tap / 3);
            uint2 A0[2], A1[2];
#pragma unroll
            for (int s = 0; s < 2; s++) {
                const unsigned* p0 = sIn + ((2 * mw + s + dy) * 18 + gID + dx) * 12 + 2 * tq;
                A0[s] = *(const uint2*)p0;
                A1[s] = *(const uint2*)(p0 + 8 * 12);
            }
#pragma unroll
            for (int nt = 0; nt < 8; nt++) {
                uint2 Bv = *(const uint2*)(sW + ((tap * 128 + nw * 64 + nt * 8 + gID) * 12) + 2 * tq);
                mma16(acc[0][nt], A0[0], A1[0], Bv);
                mma16(acc[1][nt], A0[1], A1[1], Bv);
            }
        }
        __syncthreads();
        if (c + 2 < 16) stage(c + 2, c & 1);
    }

    // ---- epilogue ----
    if (!packed) {
        unsigned* ob = (unsigned*)outv + (long)b * HP * WP * 128;
#pragma unroll
        for (int s = 0; s < 2; s++) {
            int y = y0 + 2 * mw + s;
            long rowb = (long)(y + 1) * WP * 128;
#pragma unroll
            for (int nt = 0; nt < 8; nt++) {
                int co = coB + nw * 64 + nt * 8 + (tq << 1);
                int p  = co >> 1;
                int wrd = (p >> 3) * 8 + slot_of(p & 7);
                float b0 = bias[co], b1 = bias[co + 1];
                float4 a = acc[s][nt];
                float v0 = a.x + b0, v1 = a.y + b1, v2 = a.z + b0, v3 = a.w + b1;
                if (relu) {
                    v0 = fmaxf(v0, 0.f); v1 = fmaxf(v1, 0.f);
                    v2 = fmaxf(v2, 0.f); v3 = fmaxf(v3, 0.f);
                }
                ob[rowb + (long)(x0 + gID + 1) * 128 + wrd] = pk(v0, v1);
                ob[rowb + (long)(x0 + gID + 9) * 128 + wrd] = pk(v2, v3);
            }
        }
    } else {
        float* out = (float*)outv;
#pragma unroll
        for (int s = 0; s < 2; s++) {
            int y = y0 + 2 * mw + s;
            long base  = ((long)b * TOTLOC + loc_off + (long)y * W + x0 + gID) * CHTOT + ch_off;
            long base8 = base + 8L * CHTOT;
#pragma unroll
            for (int nt = 0; nt < 8; nt++) {
                int co = coB + nw * 64 + nt * 8 + (tq << 1);
                if (co < Cout) {
                    float bv = bias[co];
                    float4 a = acc[s][nt];
                    out[base  + co] = a.x + bv;
                    out[base8 + co] = a.z + bv;
                    if (co + 1 < Cout) {
                        float bv1 = bias[co + 1];
                        out[base  + co + 1] = a.y + bv1;
                        out[base8 + co + 1] = a.w + bv1;
                    }
                }
            }
        }
    }
}

// ---------------------------------------------------------------------------
// lateral 1x1: NCHW fp32 -> padded NHWC bf16 words (4 couts / thread)
// ---------------------------------------------------------------------------
__global__ __launch_bounds__(256)
void lat_k(const float* __restrict__ in, const float* __restrict__ w,
           const float* __restrict__ bias, unsigned* __restrict__ out,
           int Cin, int H, int W)
{
    int HW = H * W;
    int idx = blockIdx.x * 256 + threadIdx.x;
    int total = B * 64 * HW;
    if (idx >= total) return;
    int px = idx % HW;
    int t  = idx / HW;
    int cg = t % 64;
    int b  = t / 64;
    int co = cg * 4;
    float a0 = bias[co], a1 = bias[co + 1], a2 = bias[co + 2], a3 = bias[co + 3];
    const float* ip = in + (long)b * Cin * HW + px;
    const float* w0 = w + (long)(co + 0) * Cin;
    const float* w1 = w + (long)(co + 1) * Cin;
    const float* w2 = w + (long)(co + 2) * Cin;
    const float* w3 = w + (long)(co + 3) * Cin;
    for (int ci = 0; ci < Cin; ci++) {
        float v = ip[(long)ci * HW];
        a0 += w0[ci] * v; a1 += w1[ci] * v; a2 += w2[ci] * v; a3 += w3[ci] * v;
    }
    int y = px / W, x = px % W;
    unsigned* base = out + ((long)(b * (H + 2) + y + 1) * (W + 2) + x + 1) * 128;
    int p0 = 2 * cg;               // channel pair indices p0, p0+1 (same group)
    int g  = p0 >> 3;
    base[g * 8 + slot_of(p0 & 7)]       = pk(a0, a1);
    base[g * 8 + slot_of((p0 + 1) & 7)] = pk(a2, a3);
}

// dst += nearest-up2(src), on bf16x2 words, identical layouts
__global__ __launch_bounds__(256)
void upadd_k(unsigned* __restrict__ dst, const unsigned* __restrict__ src, int H, int W)
{
    long idx = (long)blockIdx.x * 256 + threadIdx.x;
    long total = (long)B * H * W * 128;
    if (idx >= total) return;
    int wrd = idx & 127;
    long p = idx >> 7;
    int x = p % W;
    int y = (p / W) % H;
    int b = p / ((long)W * H);
    unsigned* d = &dst[((long)(b * (H + 2) + y + 1) * (W + 2) + x + 1) * 128 + wrd];
    const unsigned* s = &src[((long)(b * (H / 2 + 2) + (y >> 1) + 1) * (W / 2 + 2) + (x >> 1) + 1) * 128 + wrd];
    __nv_bfloat162 dv = *(__nv_bfloat162*)d, sv = *(const __nv_bfloat162*)s;
    float lo = __bfloat162float(dv.x) + __bfloat162float(sv.x);
    float hi = __bfloat162float(dv.y) + __bfloat162float(sv.y);
    *d = pk(lo, hi);
}

__global__ void zero_k(float4* p, long n4)
{
    long i = (long)blockIdx.x * blockDim.x + threadIdx.x;
    long stride = (long)gridDim.x * blockDim.x;
    for (; i < n4; i += stride) p[i] = make_float4(0.f, 0.f, 0.f, 0.f);
}

// OIHW fp32 [CoutSrc][256][9] -> bf16 words [g][tap][CoutPad][slot8] at coOff
__global__ void transform_k(const float* __restrict__ src, unsigned* __restrict__ dst,
                            int CoutSrc, int CoutPad, int coOff)
{
    long idx = (long)blockIdx.x * blockDim.x + threadIdx.x;
    long total = 9L * 128 * CoutSrc;
    if (idx >= total) return;
    int co = idx % CoutSrc;
    long r = idx / CoutSrc;
    int p = r % 128;
    int tap = r / 128;
    int g = p >> 3, w = p & 7;
    int ci = 2 * p;
    float f0 = src[(long)co * 2304 + ci * 9 + tap];
    float f1 = src[(long)co * 2304 + (ci + 1) * 9 + tap];
    dst[(((long)(g * 9 + tap) * CoutPad) + coOff + co) * 8 + slot_of(w)] = pk(f0, f1);
}

__global__ void biasbc_k(const float* bb, const float* tb, float* dst)
{
    int i = threadIdx.x;
    if (i < 4) dst[i] = bb[i];
    else if (i == 4) dst[i] = tb[0];
}

// ---------------------------------------------------------------------------
static void conv_tc(const unsigned* in, const unsigned* wgt, const float* bias, void* out,
                    int H, int W, int Cout, int CoutPad,
                    int relu, int packed, int loc, int choff)
{
    dim3 g((W / 16) * (H / 8), (CoutPad + 127) / 128, B);
    conv_tc_k<<<g, 256, SMEM_BYTES>>>(in, wgt, bias, out, H, W, Cout, CoutPad,
                                      relu, packed, loc, choff);
}

extern "C" void kernel_launch(void* const* d_in, const int* in_sizes, int n_in,
                              void* d_out, int out_size)
{
    auto idxOf = [&](int sz, int ord) -> int {
        int c = 0;
        for (int i = 0; i < n_in; i++)
            if (in_sizes[i] == sz) { if (c == ord) return i; c++; }
        return -1;
    };
    const int i_c3  = idxOf(2 * 64 * 64 * 64, 0);
    const int i_c4  = idxOf(2 * 160 * 32 * 32, 0);
    const int i_c5  = idxOf(2 * 400 * 16 * 16, 0);
    const int i_l3w = idxOf(256 * 64, 0);
    const int i_l4w = idxOf(256 * 160, 0);
    const int i_l5w = idxOf(256 * 400, 0);
    const int i_o3w = idxOf(256 * 256 * 9, 0);
    const int i_o4w = idxOf(256 * 256 * 9, 1);
    const int i_o5w = idxOf(256 * 256 * 9, 2);
    const int i_scw = idxOf(4 * 256 * 256 * 9, 0);
    const int i_sbw = idxOf(4 * 256 * 256 * 9, 1);
    const int i_cw  = idxOf(80 * 256 * 9, 0);
    const int i_bw  = idxOf(4 * 256 * 9, 0);
    const int i_tw  = idxOf(1 * 256 * 9, 0);

    const float* c3 = (const float*)d_in[i_c3];
    const float* c4 = (const float*)d_in[i_c4];
    const float* c5 = (const float*)d_in[i_c5];
    const float* l3w = (const float*)d_in[i_l3w]; const float* l3b = (const float*)d_in[i_l3w + 1];
    const float* l4w = (const float*)d_in[i_l4w]; const float* l4b = (const float*)d_in[i_l4w + 1];
    const float* l5w = (const float*)d_in[i_l5w]; const float* l5b = (const float*)d_in[i_l5w + 1];
    const float* o3w = (const float*)d_in[i_o3w]; const float* o3b = (const float*)d_in[i_o3w + 1];
    const float* o4w = (const float*)d_in[i_o4w]; const float* o4b = (const float*)d_in[i_o4w + 1];
    const float* o5w = (const float*)d_in[i_o5w]; const float* o5b = (const float*)d_in[i_o5w + 1];
    const float* scw = (const float*)d_in[i_scw]; const float* scb = (const float*)d_in[i_scw + 1];
    const float* sbw = (const float*)d_in[i_sbw]; const float* sbb = (const float*)d_in[i_sbw + 1];
    const float* cw  = (const float*)d_in[i_cw];  const float* cb  = (const float*)d_in[i_cw + 1];
    const float* bw  = (const float*)d_in[i_bw];  const float* bb  = (const float*)d_in[i_bw + 1];
    const float* tw  = (const float*)d_in[i_tw];  const float* tb  = (const float*)d_in[i_tw + 1];

    unsigned *lat3, *lat4, *lat5, *p3, *p4, *p5, *tA3, *tB3, *tA4, *tB4, *tA5, *tB5;
    unsigned *wt, *wt_cls, *wt_bc;
    float* bias_bc;
    cudaGetSymbolAddress((void**)&lat3, g_lat3); cudaGetSymbolAddress((void**)&lat4, g_lat4);
    cudaGetSymbolAddress((void**)&lat5, g_lat5); cudaGetSymbolAddress((void**)&p3, g_p3);
    cudaGetSymbolAddress((void**)&p4, g_p4);     cudaGetSymbolAddress((void**)&p5, g_p5);
    cudaGetSymbolAddress((void**)&tA3, g_tA3);   cudaGetSymbolAddress((void**)&tB3, g_tB3);
    cudaGetSymbolAddress((void**)&tA4, g_tA4);   cudaGetSymbolAddress((void**)&tB4, g_tB4);
    cudaGetSymbolAddress((void**)&tA5, g_tA5);   cudaGetSymbolAddress((void**)&tB5, g_tB5);
    cudaGetSymbolAddress((void**)&wt, g_wt);     cudaGetSymbolAddress((void**)&wt_cls, g_wt_cls);
    cudaGetSymbolAddress((void**)&wt_bc, g_wt_bc); cudaGetSymbolAddress((void**)&bias_bc, g_bias_bc);

    cudaFuncSetAttribute(conv_tc_k, cudaFuncAttributeMaxDynamicSharedMemorySize, SMEM_BYTES);

    float* out = (float*)d_out;

    // ---- zero bf16 activation buffers (borders must be 0) + padded weights ----
    {
        long n3 = 2L * 66 * 66 * 128 / 4, n4 = 2L * 34 * 34 * 128 / 4, n5 = 2L * 18 * 18 * 128 / 4;
        zero_k<<<256, 256>>>((float4*)lat3, n3); zero_k<<<256, 256>>>((float4*)p3, n3);
        zero_k<<<256, 256>>>((float4*)tA3, n3);  zero_k<<<256, 256>>>((float4*)tB3, n3);
        zero_k<<<128, 256>>>((float4*)lat4, n4); zero_k<<<128, 256>>>((float4*)p4, n4);
        zero_k<<<128, 256>>>((float4*)tA4, n4);  zero_k<<<128, 256>>>((float4*)tB4, n4);
        zero_k<<<64, 256>>>((float4*)lat5, n5);  zero_k<<<64, 256>>>((float4*)p5, n5);
        zero_k<<<64, 256>>>((float4*)tA5, n5);   zero_k<<<64, 256>>>((float4*)tB5, n5);
        zero_k<<<64, 256>>>((float4*)wt_cls, W128 / 4);
        zero_k<<<64, 256>>>((float4*)wt_bc,  W128 / 4);
    }

    // ---- weight transforms ----
    {
        long tot = 9L * 128 * 256;
        int gb = (int)((tot + 255) / 256);
        transform_k<<<gb, 256>>>(o3w, wt + 0L * W256, 256, 256, 0);
        transform_k<<<gb, 256>>>(o4w, wt + 1L * W256, 256, 256, 0);
        transform_k<<<gb, 256>>>(o5w, wt + 2L * W256, 256, 256, 0);
        for (int i = 0; i < 4; i++) {
            transform_k<<<gb, 256>>>(scw + (long)i * 256 * 256 * 9, wt + (3 + i) * (long)W256, 256, 256, 0);
            transform_k<<<gb, 256>>>(sbw + (long)i * 256 * 256 * 9, wt + (7 + i) * (long)W256, 256, 256, 0);
        }
        long totc = 9L * 128 * 80;
        transform_k<<<(int)((totc + 255) / 256), 256>>>(cw, wt_cls, 80, 128, 0);
        long totb = 9L * 128 * 4;
        transform_k<<<(int)((totb + 255) / 256), 256>>>(bw, wt_bc, 4, 128, 0);
        long tott = 9L * 128 * 1;
        transform_k<<<(int)((tott + 255) / 256), 256>>>(tw, wt_bc, 1, 128, 4);
        biasbc_k<<<1, 8>>>(bb, tb, bias_bc);
    }

    // ---- FPN ----
    lat_k<<<(B * 64 * 256 + 255) / 256, 256>>>(c5, l5w, l5b, lat5, 400, 16, 16);
    lat_k<<<(B * 64 * 1024 + 255) / 256, 256>>>(c4, l4w, l4b, lat4, 160, 32, 32);
    lat_k<<<(B * 64 * 4096 + 255) / 256, 256>>>(c3, l3w, l3b, lat3, 64, 64, 64);

    conv_tc(lat5, wt + 2L * W256, o5b, p5, 16, 16, 256, 256, 0, 0, 0, 0);
    {
        long n = (long)B * 32 * 32 * 128;
        upadd_k<<<(int)((n + 255) / 256), 256>>>(lat4, lat5, 32, 32);
    }
    conv_tc(lat4, wt + 1L * W256, o4b, p4, 32, 32, 256, 256, 0, 0, 0, 0);
    {
        long n = (long)B * 64 * 64 * 128;
        upadd_k<<<(int)((n + 255) / 256), 256>>>(lat3, lat4, 64, 64);
    }
    conv_tc(lat3, wt + 0L * W256, o3b, p3, 64, 64, 256, 256, 0, 0, 0, 0);

    // ---- heads ----
    struct Lvl { unsigned *p, *tA, *tB; int H, W, loc; };
    Lvl lv[3] = { { p3, tA3, tB3, 64, 64, 0 },
                  { p4, tA4, tB4, 32, 32, 4096 },
                  { p5, tA5, tB5, 16, 16, 5120 } };

    for (int L = 0; L < 3; L++) {
        const unsigned* src = lv[L].p;
        for (int i = 0; i < 4; i++) {
            unsigned* dst = (i & 1) ? lv[L].tB : lv[L].tA;
            conv_tc(src, wt + (3 + i) * (long)W256, scb + i * 256, dst,
                    lv[L].H, lv[L].W, 256, 256, 1, 0, 0, 0);
            src = dst;
        }
        conv_tc(src, wt_cls, cb, out, lv[L].H, lv[L].W, NUMC, 128, 0, 1, lv[L].loc, 0);

        src = lv[L].p;
        for (int i = 0; i < 4; i++) {
            unsigned* dst = (i & 1) ? lv[L].tB : lv[L].tA;
            conv_tc(src, wt + (7 + i) * (long)W256, sbb + i * 256, dst,
                    lv[L].H, lv[L].W, 256, 256, 1, 0, 0, 0);
            src = dst;
        }
        conv_tc(src, wt_bc, bias_bc, out, lv[L].H, lv[L].W, 5, 128, 0, 1, lv[L].loc, 80);
    }
    (void)out_size;
}

// round 13
// speedup vs baseline: 6.7481x; 2.4788x over previous
#include <cuda_runtime.h>
#include <cuda_bf16.h>
#include <cstdint>

// ---------------------------------------------------------------------------
// FCOS head on GB300 — round 13: bf16 m16n8k16 mma.sync convs (R7 kernel,
// proven) + fused multi-job launches (JobSet) to fill the chip.
// tcgen05 is confirmed unavailable (harness lowers via compute_103 target).
// ---------------------------------------------------------------------------

#define NUMC 80
#define CHTOT 85
#define TOTLOC 5376
#define B 2

// ---- activation pool: padded NHWC bf16x2 words, slot-permuted, 6 bufs/level
#define S3W (2 * 66 * 66 * 128)
#define S4W (2 * 34 * 34 * 128)
#define S5W (2 * 18 * 18 * 128)
__device__ unsigned g_act[6 * S3W + 6 * S4W + 6 * S5W];

// ---- transformed bf16 weights: [group16][tap9][coutPad][8 words], permuted
#define W256 (16 * 9 * 256 * 8)
#define W128 (16 * 9 * 128 * 8)
__device__ unsigned g_wt[11 * W256];     // out3/4/5, stem_cls0-3, stem_box0-3
__device__ unsigned g_wt_cls[W128];      // cls, pad 128 (pre-zeroed)
__device__ unsigned g_wt_bc [W128];      // box(4)+ctr(1), pad 128 (pre-zeroed)
__device__ float    g_bias_bc[5];

__device__ __forceinline__ unsigned pk(float a, float b) {
    __nv_bfloat162 h = __floats2bfloat162_rn(a, b);
    return *(unsigned*)&h;
}
__device__ __forceinline__ int slot_of(int w) { return ((w & 3) << 1) | (w >> 2); }

__device__ __forceinline__ void cpa16(void* smem, const void* g) {
    unsigned s = (unsigned)__cvta_generic_to_shared(smem);
    asm volatile("cp.async.cg.shared.global [%0], [%1], 16;" :: "r"(s), "l"(g) : "memory");
}

__device__ __forceinline__ void mma16(float4& d, uint2 A0, uint2 A1, uint2 Bv) {
    asm volatile(
        "mma.sync.aligned.m16n8k16.row.col.f32.bf16.bf16.f32 "
        "{%0,%1,%2,%3}, {%4,%5,%6,%7}, {%8,%9}, {%0,%1,%2,%3};\n"
        : "+f"(d.x), "+f"(d.y), "+f"(d.z), "+f"(d.w)
        : "r"(A0.x), "r"(A1.x), "r"(A0.y), "r"(A1.y),
          "r"(Bv.x), "r"(Bv.y));
}

// ---------------------------------------------------------------------------
// bf16 tensor-core 3x3 conv (R7 body), multi-job dispatch.
// CTA: 128 pixels (8r x 16c) x 128 couts; 8 warps = 4m x 2n; 16 K-chunks of
// 16 cin, cp.async double-buffered.  flags: 1=relu, 2=packed output.
// ---------------------------------------------------------------------------
#define SIN_W (180 * 12)
#define SW_W  (9 * 128 * 12)
#define BUF_W (SIN_W + SW_W)
#define SMEM_BYTES (2 * BUF_W * 4)

struct Job {
    const unsigned* src;
    const unsigned* wgt;
    const float* bias;
    void* dst;
    int H, W, start, nCoB, Cout, flags, loc_off, ch_off;
};
struct JobSet { Job j[6]; int nj; };

__global__ __launch_bounds__(256)
void conv_tc_k(JobSet js)
{
    extern __shared__ unsigned sm[];

    int ji = 0;
    for (int k = 1; k < js.nj; k++)
        if ((int)blockIdx.x >= js.j[k].start) ji = k;
    const Job jb = js.j[ji];
    const int H = jb.H, W = jb.W;
    const int Cout = jb.Cout, CoutPad = jb.nCoB << 7;
    const int relu = jb.flags & 1, packed = jb.flags & 2;

    const int local = blockIdx.x - jb.start;
    const int nT = (W >> 4) * (H >> 3);
    const int t = local % nT;
    const int rest = local / nT;
    const int coB = (rest % jb.nCoB) << 7;
    const int b = rest / jb.nCoB;

    const int tid = threadIdx.x, lane = tid & 31, wrp = tid >> 5;
    const int mw = wrp >> 1, nw = wrp & 1, gID = lane >> 2, tq = lane & 3;
    const int tilesX = W >> 4;
    const int x0 = (t % tilesX) << 4;
    const int y0 = (t / tilesX) << 3;
    const int HP = H + 2, WP = W + 2;

    const unsigned* inB = jb.src + (long)b * HP * WP * 128;

    float4 acc[2][8];
#pragma unroll
    for (int s = 0; s < 2; s++)
#pragma unroll
        for (int nt = 0; nt < 8; nt++) acc[s][nt] = make_float4(0.f, 0.f, 0.f, 0.f);

    auto stage = [&](int g, int buf) {
        unsigned* sIn = sm + buf * BUF_W;
        unsigned* sW  = sIn + SIN_W;
        for (int i = tid; i < 360; i += 256) {
            int pix = i >> 1, half = i & 1;
            int rw = pix / 18, cl = pix - rw * 18;
            const unsigned* src = inB + ((long)(y0 + rw) * WP + (x0 + cl)) * 128 + g * 8 + half * 4;
            cpa16(&sIn[pix * 12 + half * 4], src);
        }
        for (int i = tid; i < 2304; i += 256) {
            int half = i & 1;
            int n    = (i >> 1) & 127;
            int tap  = i >> 8;
            const unsigned* src = jb.wgt + (((long)(g * 9 + tap) * CoutPad) + coB + n) * 8 + half * 4;
            cpa16(&sW[(tap * 128 + n) * 12 + half * 4], src);
        }
        asm volatile("cp.async.commit_group;" ::: "memory");
    };

    stage(0, 0);
    stage(1, 1);

    for (int c = 0; c < 16; c++) {
        if (c < 15) asm volatile("cp.async.wait_group 1;" ::: "memory");
        else        asm volatile("cp.async.wait_group 0;" ::: "memory");
        __syncthreads();

        const unsigned* sIn = sm + (c & 1) * BUF_W;
        const unsigned* sW  = sIn + SIN_W;

#pragma unroll
        for (int tap = 0; tap < 9; tap++) {
            const int dy = tap / 3, dx = tap - 3 * (tap / 3);
            uint2 A0[2], A1[2];
#pragma unroll
            for (int s = 0; s < 2; s++) {
                const unsigned* p0 = sIn + ((2 * mw + s + dy) * 18 + gID + dx) * 12 + 2 * tq;
                A0[s] = *(const uint2*)p0;
                A1[s] = *(const uint2*)(p0 + 8 * 12);
            }
#pragma unroll
            for (int nt = 0; nt < 8; nt++) {
                uint2 Bv = *(const uint2*)(sW + ((tap * 128 + nw * 64 + nt * 8 + gID) * 12) + 2 * tq);
                mma16(acc[0][nt], A0[0], A1[0], Bv);
                mma16(acc[1][nt], A0[1], A1[1], Bv);
            }
        }
        __syncthreads();
        if (c + 2 < 16) stage(c + 2, c & 1);
    }

    // ---- epilogue ----
    if (!packed) {
        unsigned* ob = (unsigned*)jb.dst + (long)b * HP * WP * 128;
#pragma unroll
        for (int s = 0; s < 2; s++) {
            int y = y0 + 2 * mw + s;
            long rowb = (long)(y + 1) * WP * 128;
#pragma unroll
            for (int nt = 0; nt < 8; nt++) {
                int co = coB + nw * 64 + nt * 8 + (tq << 1);
                int p  = co >> 1;
                int wrd = (p >> 3) * 8 + slot_of(p & 7);
                float b0 = jb.bias[co], b1 = jb.bias[co + 1];
                float4 a = acc[s][nt];
                float v0 = a.x + b0, v1 = a.y + b1, v2 = a.z + b0, v3 = a.w + b1;
                if (relu) {
                    v0 = fmaxf(v0, 0.f); v1 = fmaxf(v1, 0.f);
                    v2 = fmaxf(v2, 0.f); v3 = fmaxf(v3, 0.f);
                }
                ob[rowb + (long)(x0 + gID + 1) * 128 + wrd] = pk(v0, v1);
                ob[rowb + (long)(x0 + gID + 9) * 128 + wrd] = pk(v2, v3);
            }
        }
    } else {
        float* out = (float*)jb.dst;
#pragma unroll
        for (int s = 0; s < 2; s++) {
            int y = y0 + 2 * mw + s;
            long base  = ((long)b * TOTLOC + jb.loc_off + (long)y * W + x0 + gID) * CHTOT + jb.ch_off;
            long base8 = base + 8L * CHTOT;
#pragma unroll
            for (int nt = 0; nt < 8; nt++) {
                int co = coB + nw * 64 + nt * 8 + (tq << 1);
                if (co < Cout) {
                    float bv = jb.bias[co];
                    float4 a = acc[s][nt];
                    out[base  + co] = a.x + bv;
                    out[base8 + co] = a.z + bv;
                    if (co + 1 < Cout) {
                        float bv1 = jb.bias[co + 1];
                        out[base  + co + 1] = a.y + bv1;
                        out[base8 + co + 1] = a.w + bv1;
                    }
                }
            }
        }
    }
}

// ---------------------------------------------------------------------------
// lateral 1x1: NCHW fp32 -> padded NHWC bf16 words (slot-permuted)
// ---------------------------------------------------------------------------
__global__ __launch_bounds__(256)
void lat_k(const float* __restrict__ in, const float* __restrict__ w,
           const float* __restrict__ bias, unsigned* __restrict__ out,
           int Cin, int H, int W)
{
    int HW = H * W;
    int idx = blockIdx.x * 256 + threadIdx.x;
    int total = B * 64 * HW;
    if (idx >= total) return;
    int px = idx % HW;
    int t  = idx / HW;
    int cg = t % 64;
    int b  = t / 64;
    int co = cg * 4;
    float a0 = bias[co], a1 = bias[co + 1], a2 = bias[co + 2], a3 = bias[co + 3];
    const float* ip = in + (long)b * Cin * HW + px;
    const float* w0 = w + (long)(co + 0) * Cin;
    const float* w1 = w + (long)(co + 1) * Cin;
    const float* w2 = w + (long)(co + 2) * Cin;
    const float* w3 = w + (long)(co + 3) * Cin;
    for (int ci = 0; ci < Cin; ci++) {
        float v = ip[(long)ci * HW];
        a0 += w0[ci] * v; a1 += w1[ci] * v; a2 += w2[ci] * v; a3 += w3[ci] * v;
    }
    int y = px / W, x = px % W;
    unsigned* base = out + ((long)(b * (H + 2) + y + 1) * (W + 2) + x + 1) * 128;
    int p0 = 2 * cg;
    int g  = p0 >> 3;
    base[g * 8 + slot_of(p0 & 7)]       = pk(a0, a1);
    base[g * 8 + slot_of((p0 + 1) & 7)] = pk(a2, a3);
}

// dst += nearest-up2(src), bf16x2 words, identical layouts
__global__ __launch_bounds__(256)
void upadd_k(unsigned* __restrict__ dst, const unsigned* __restrict__ src, int H, int W)
{
    long idx = (long)blockIdx.x * 256 + threadIdx.x;
    long total = (long)B * H * W * 128;
    if (idx >= total) return;
    int wrd = idx & 127;
    long p = idx >> 7;
    int x = p % W;
    int y = (p / W) % H;
    int b = p / ((long)W * H);
    unsigned* d = &dst[((long)(b * (H + 2) + y + 1) * (W + 2) + x + 1) * 128 + wrd];
    const unsigned* s = &src[((long)(b * (H / 2 + 2) + (y >> 1) + 1) * (W / 2 + 2) + (x >> 1) + 1) * 128 + wrd];
    __nv_bfloat162 dv = *(__nv_bfloat162*)d, sv = *(const __nv_bfloat162*)s;
    *d = pk(__bfloat162float(dv.x) + __bfloat162float(sv.x),
            __bfloat162float(dv.y) + __bfloat162float(sv.y));
}

__global__ void zero_k(float4* p, long n4)
{
    long i = (long)blockIdx.x * blockDim.x + threadIdx.x;
    long stride = (long)gridDim.x * blockDim.x;
    for (; i < n4; i += stride) p[i] = make_float4(0.f, 0.f, 0.f, 0.f);
}

// OIHW fp32 [CoutSrc][256][9] -> bf16 words [g][tap][CoutPad][slot8] at coOff
__global__ void transform_k(const float* __restrict__ src, unsigned* __restrict__ dst,
                            int CoutSrc, int CoutPad, int coOff)
{
    long idx = (long)blockIdx.x * blockDim.x + threadIdx.x;
    long total = 9L * 128 * CoutSrc;
    if (idx >= total) return;
    int co = idx % CoutSrc;
    long r = idx / CoutSrc;
    int p = r % 128;
    int tap = r / 128;
    int g = p >> 3, w = p & 7;
    int ci = 2 * p;
    float f0 = src[(long)co * 2304 + ci * 9 + tap];
    float f1 = src[(long)co * 2304 + (ci + 1) * 9 + tap];
    dst[(((long)(g * 9 + tap) * CoutPad) + coOff + co) * 8 + slot_of(w)] = pk(f0, f1);
}

__global__ void biasbc_k(const float* bb, const float* tb, float* dst)
{
    int i = threadIdx.x;
    if (i < 4) dst[i] = bb[i];
    else if (i == 4) dst[i] = tb[0];
}

// ---------------------------------------------------------------------------
extern "C" void kernel_launch(void* const* d_in, const int* in_sizes, int n_in,
                              void* d_out, int out_size)
{
    auto idxOf = [&](int sz, int ord) -> int {
        int c = 0;
        for (int i = 0; i < n_in; i++)
            if (in_sizes[i] == sz) { if (c == ord) return i; c++; }
        return -1;
    };
    const int i_c3  = idxOf(2 * 64 * 64 * 64, 0);
    const int i_c4  = idxOf(2 * 160 * 32 * 32, 0);
    const int i_c5  = idxOf(2 * 400 * 16 * 16, 0);
    const int i_l3w = idxOf(256 * 64, 0);
    const int i_l4w = idxOf(256 * 160, 0);
    const int i_l5w = idxOf(256 * 400, 0);
    const int i_o3w = idxOf(256 * 256 * 9, 0);
    const int i_o4w = idxOf(256 * 256 * 9, 1);
    const int i_o5w = idxOf(256 * 256 * 9, 2);
    const int i_scw = idxOf(4 * 256 * 256 * 9, 0);
    const int i_sbw = idxOf(4 * 256 * 256 * 9, 1);
    const int i_cw  = idxOf(80 * 256 * 9, 0);
    const int i_bw  = idxOf(4 * 256 * 9, 0);
    const int i_tw  = idxOf(1 * 256 * 9, 0);

    const float* c3 = (const float*)d_in[i_c3];
    const float* c4 = (const float*)d_in[i_c4];
    const float* c5 = (const float*)d_in[i_c5];
    const float* l3w = (const float*)d_in[i_l3w]; const float* l3b = (const float*)d_in[i_l3w + 1];
    const float* l4w = (const float*)d_in[i_l4w]; const float* l4b = (const float*)d_in[i_l4w + 1];
    const float* l5w = (const float*)d_in[i_l5w]; const float* l5b = (const float*)d_in[i_l5w + 1];
    const float* o3w = (const float*)d_in[i_o3w]; const float* o3b = (const float*)d_in[i_o3w + 1];
    const float* o4w = (const float*)d_in[i_o4w]; const float* o4b = (const float*)d_in[i_o4w + 1];
    const float* o5w = (const float*)d_in[i_o5w]; const float* o5b = (const float*)d_in[i_o5w + 1];
    const float* scw = (const float*)d_in[i_scw]; const float* scb = (const float*)d_in[i_scw + 1];
    const float* sbw = (const float*)d_in[i_sbw]; const float* sbb = (const float*)d_in[i_sbw + 1];
    const float* cw  = (const float*)d_in[i_cw];  const float* cb  = (const float*)d_in[i_cw + 1];
    const float* bw  = (const float*)d_in[i_bw];  const float* bb  = (const float*)d_in[i_bw + 1];
    const float* tw  = (const float*)d_in[i_tw];  const float* tb  = (const float*)d_in[i_tw + 1];

    unsigned *act, *wt, *wt_cls, *wt_bc;
    float* bias_bc;
    cudaGetSymbolAddress((void**)&act, g_act);
    cudaGetSymbolAddress((void**)&wt, g_wt);
    cudaGetSymbolAddress((void**)&wt_cls, g_wt_cls);
    cudaGetSymbolAddress((void**)&wt_bc, g_wt_bc);
    cudaGetSymbolAddress((void**)&bias_bc, g_bias_bc);

    // buffer carve per level: 0=lat, 1=p, 2=tA, 3=tB, 4=tC, 5=tD
    unsigned* L3p[6]; unsigned* L4p[6]; unsigned* L5p[6];
    for (int i = 0; i < 6; i++) L3p[i] = act + (long)i * S3W;
    unsigned* b4 = act + 6L * S3W;
    for (int i = 0; i < 6; i++) L4p[i] = b4 + (long)i * S4W;
    unsigned* b5 = b4 + 6L * S4W;
    for (int i = 0; i < 6; i++) L5p[i] = b5 + (long)i * S5W;

    cudaFuncSetAttribute(conv_tc_k, cudaFuncAttributeMaxDynamicSharedMemorySize, SMEM_BYTES);

    float* out = (float*)d_out;

    // ---- zero activation pool (borders must stay 0) + padded small weights ----
    zero_k<<<512, 256>>>((float4*)act, (long)(6L * S3W + 6L * S4W + 6L * S5W) / 4);
    zero_k<<<64, 256>>>((float4*)wt_cls, W128 / 4);
    zero_k<<<64, 256>>>((float4*)wt_bc,  W128 / 4);

    // ---- weight transforms ----
    {
        long tot = 9L * 128 * 256;
        int gb = (int)((tot + 255) / 256);
        transform_k<<<gb, 256>>>(o3w, wt + 0L * W256, 256, 256, 0);
        transform_k<<<gb, 256>>>(o4w, wt + 1L * W256, 256, 256, 0);
        transform_k<<<gb, 256>>>(o5w, wt + 2L * W256, 256, 256, 0);
        for (int i = 0; i < 4; i++) {
            transform_k<<<gb, 256>>>(scw + (long)i * 256 * 256 * 9, wt + (3 + i) * (long)W256, 256, 256, 0);
            transform_k<<<gb, 256>>>(sbw + (long)i * 256 * 256 * 9, wt + (7 + i) * (long)W256, 256, 256, 0);
        }
        long totc = 9L * 128 * 80;
        transform_k<<<(int)((totc + 255) / 256), 256>>>(cw, wt_cls, 80, 128, 0);
        long totb = 9L * 128 * 4;
        transform_k<<<(int)((totb + 255) / 256), 256>>>(bw, wt_bc, 4, 128, 0);
        long tott = 9L * 128 * 1;
        transform_k<<<(int)((tott + 255) / 256), 256>>>(tw, wt_bc, 1, 128, 4);
        biasbc_k<<<1, 8>>>(bb, tb, bias_bc);
    }

    // ---- FPN laterals ----
    lat_k<<<(B * 64 * 256 + 255) / 256, 256>>>(c5, l5w, l5b, L5p[0], 400, 16, 16);
    lat_k<<<(B * 64 * 1024 + 255) / 256, 256>>>(c4, l4w, l4b, L4p[0], 160, 32, 32);
    lat_k<<<(B * 64 * 4096 + 255) / 256, 256>>>(c3, l3w, l3b, L3p[0], 64, 64, 64);

    const int nT[3] = { 32, 8, 2 };
    const int Hs[3] = { 64, 32, 16 }, Ws[3] = { 64, 32, 16 };
    const int locs[3] = { 0, 4096, 5120 };

    auto mkJob = [&](const unsigned* src, const unsigned* w, const float* bias,
                     void* dst, int L, int start, int nCoB, int Cout, int flags,
                     int loc, int ch) {
        Job j;
        j.src = src; j.wgt = w; j.bias = bias; j.dst = dst;
        j.H = Hs[L]; j.W = Ws[L]; j.start = start; j.nCoB = nCoB;
        j.Cout = Cout; j.flags = flags; j.loc_off = loc; j.ch_off = ch;
        return j;
    };

    // ---- FPN 3x3 out convs (serial: p5 -> upadd -> p4 -> upadd -> p3) ----
    {
        JobSet js; js.nj = 1;
        js.j[0] = mkJob(L5p[0], wt + 2L * W256, o5b, L5p[1], 2, 0, 2, 256, 0, 0, 0);
        conv_tc_k<<<nT[2] * 4, 256, SMEM_BYTES>>>(js);
        long n = (long)B * 32 * 32 * 128;
        upadd_k<<<(int)((n + 255) / 256), 256>>>(L4p[0], L5p[0], 32, 32);
        js.j[0] = mkJob(L4p[0], wt + 1L * W256, o4b, L4p[1], 1, 0, 2, 256, 0, 0, 0);
        conv_tc_k<<<nT[1] * 4, 256, SMEM_BYTES>>>(js);
        n = (long)B * 64 * 64 * 128;
        upadd_k<<<(int)((n + 255) / 256), 256>>>(L3p[0], L4p[0], 64, 64);
        js.j[0] = mkJob(L3p[0], wt + 0L * W256, o3b, L3p[1], 0, 0, 2, 256, 0, 0, 0);
        conv_tc_k<<<nT[0] * 4, 256, SMEM_BYTES>>>(js);
    }

    // ---- fused stems: 4 launches, each = 3 levels x 2 branches (336 CTAs) ----
    // cls chain: p(1) -> tA(2) -> tB(3) -> tA(2) -> tB(3)
    // box chain: p(1) -> tC(4) -> tD(5) -> tC(4) -> tD(5)
    unsigned** Lp[3] = { L3p, L4p, L5p };
    for (int i = 0; i < 4; i++) {
        int sc_s = (i == 0) ? 1 : ((i & 1) ? 2 : 3);
        int sc_d = (i & 1) ? 3 : 2;
        int sb_s = (i == 0) ? 1 : ((i & 1) ? 4 : 5);
        int sb_d = (i & 1) ? 5 : 4;
        JobSet js; js.nj = 6;
        int start = 0;
        for (int L = 0; L < 3; L++) {
            js.j[2 * L] = mkJob(Lp[L][sc_s], wt + (3 + i) * (long)W256, scb + i * 256,
                                Lp[L][sc_d], L, start, 2, 256, 1, 0, 0);
            start += nT[L] * 4;
            js.j[2 * L + 1] = mkJob(Lp[L][sb_s], wt + (7 + i) * (long)W256, sbb + i * 256,
                                    Lp[L][sb_d], L, start, 2, 256, 1, 0, 0);
            start += nT[L] * 4;
        }
        conv_tc_k<<<start, 256, SMEM_BYTES>>>(js);
    }

    // ---- fused finals: cls (from tB=3) + box/ctr (from tD=5), 168 CTAs ----
    {
        JobSet js; js.nj = 6;
        int start = 0;
        for (int L = 0; L < 3; L++) {
            js.j[L] = mkJob(Lp[L][3], wt_cls, cb, out, L, start, 1, NUMC, 2, locs[L], 0);
            start += nT[L] * 2;
        }
        for (int L = 0; L < 3; L++) {
            js.j[3 + L] = mkJob(Lp[L][5], wt_bc, bias_bc, out, L, start, 1, 5, 2, locs[L], 80);
            start += nT[L] * 2;
        }
        conv_tc_k<<<start, 256, SMEM_BYTES>>>(js);
    }
    (void)out_size;
}

// round 14
// speedup vs baseline: 8.1900x; 1.2137x over previous
#include <cuda_runtime.h>
#include <cuda_bf16.h>
#include <cstdint>

// ---------------------------------------------------------------------------
// FCOS head on GB300 — round 14: R13 bf16 mma.sync conv + slim smem (8-word
// stride, conflict-free verified) -> 2 CTAs/SM, and fused weight transforms.
// ---------------------------------------------------------------------------

#define NUMC 80
#define CHTOT 85
#define TOTLOC 5376
#define B 2

// ---- activation pool: padded NHWC bf16x2 words, slot-permuted, 6 bufs/level
#define S3W (2 * 66 * 66 * 128)
#define S4W (2 * 34 * 34 * 128)
#define S5W (2 * 18 * 18 * 128)
__device__ unsigned g_act[6 * S3W + 6 * S4W + 6 * S5W];

// ---- transformed bf16 weights: [group16][tap9][coutPad][8 words], permuted
#define W256 (16 * 9 * 256 * 8)
#define W128 (16 * 9 * 128 * 8)
__device__ unsigned g_wt[11 * W256];     // out3/4/5, stem_cls0-3, stem_box0-3
__device__ unsigned g_wt_cls[W128];      // cls, pad 128 (pre-zeroed)
__device__ unsigned g_wt_bc [W128];      // box(4)+ctr(1), pad 128 (pre-zeroed)
__device__ float    g_bias_bc[5];

__device__ __forceinline__ unsigned pk(float a, float b) {
    __nv_bfloat162 h = __floats2bfloat162_rn(a, b);
    return *(unsigned*)&h;
}
__device__ __forceinline__ int slot_of(int w) { return ((w & 3) << 1) | (w >> 2); }

__device__ __forceinline__ void cpa16(void* smem, const void* g) {
    unsigned s = (unsigned)__cvta_generic_to_shared(smem);
    asm volatile("cp.async.cg.shared.global [%0], [%1], 16;" :: "r"(s), "l"(g) : "memory");
}

__device__ __forceinline__ void mma16(float4& d, uint2 A0, uint2 A1, uint2 Bv) {
    asm volatile(
        "mma.sync.aligned.m16n8k16.row.col.f32.bf16.bf16.f32 "
        "{%0,%1,%2,%3}, {%4,%5,%6,%7}, {%8,%9}, {%0,%1,%2,%3};\n"
        : "+f"(d.x), "+f"(d.y), "+f"(d.z), "+f"(d.w)
        : "r"(A0.x), "r"(A1.x), "r"(A0.y), "r"(A1.y),
          "r"(Bv.x), "r"(Bv.y));
}

// ---------------------------------------------------------------------------
// bf16 tensor-core 3x3 conv, multi-job dispatch, 8-word smem stride.
// CTA: 128 pixels (8r x 16c) x 128 couts; 8 warps = 4m x 2n; 16 K-chunks of
// 16 cin, cp.async double-buffered.  flags: 1=relu, 2=packed output.
// ---------------------------------------------------------------------------
#define SIN_W (180 * 8)
#define SW_W  (9 * 128 * 8)
#define BUF_W (SIN_W + SW_W)
#define SMEM_BYTES (2 * BUF_W * 4)       // 85,248 bytes -> 2 CTAs/SM

struct Job {
    const unsigned* src;
    const unsigned* wgt;
    const float* bias;
    void* dst;
    int H, W, start, nCoB, Cout, flags, loc_off, ch_off;
};
struct JobSet { Job j[6]; int nj; };

__global__ __launch_bounds__(256, 2)
void conv_tc_k(JobSet js)
{
    extern __shared__ unsigned sm[];

    int ji = 0;
    for (int k = 1; k < js.nj; k++)
        if ((int)blockIdx.x >= js.j[k].start) ji = k;
    const Job jb = js.j[ji];
    const int H = jb.H, W = jb.W;
    const int Cout = jb.Cout, CoutPad = jb.nCoB << 7;
    const int relu = jb.flags & 1, packed = jb.flags & 2;

    const int local = blockIdx.x - jb.start;
    const int nT = (W >> 4) * (H >> 3);
    const int t = local % nT;
    const int rest = local / nT;
    const int coB = (rest % jb.nCoB) << 7;
    const int b = rest / jb.nCoB;

    const int tid = threadIdx.x, lane = tid & 31, wrp = tid >> 5;
    const int mw = wrp >> 1, nw = wrp & 1, gID = lane >> 2, tq = lane & 3;
    const int tilesX = W >> 4;
    const int x0 = (t % tilesX) << 4;
    const int y0 = (t / tilesX) << 3;
    const int HP = H + 2, WP = W + 2;

    const unsigned* inB = jb.src + (long)b * HP * WP * 128;

    float4 acc[2][8];
#pragma unroll
    for (int s = 0; s < 2; s++)
#pragma unroll
        for (int nt = 0; nt < 8; nt++) acc[s][nt] = make_float4(0.f, 0.f, 0.f, 0.f);

    auto stage = [&](int g, int buf) {
        unsigned* sIn = sm + buf * BUF_W;
        unsigned* sW  = sIn + SIN_W;
        for (int i = tid; i < 360; i += 256) {
            int pix = i >> 1, half = i & 1;
            int rw = pix / 18, cl = pix - rw * 18;
            const unsigned* src = inB + ((long)(y0 + rw) * WP + (x0 + cl)) * 128 + g * 8 + half * 4;
            cpa16(&sIn[pix * 8 + half * 4], src);
        }
        for (int i = tid; i < 2304; i += 256) {
            int half = i & 1;
            int n    = (i >> 1) & 127;
            int tap  = i >> 8;
            const unsigned* src = jb.wgt + (((long)(g * 9 + tap) * CoutPad) + coB + n) * 8 + half * 4;
            cpa16(&sW[(tap * 128 + n) * 8 + half * 4], src);
        }
        asm volatile("cp.async.commit_group;" ::: "memory");
    };

    stage(0, 0);
    stage(1, 1);

    for (int c = 0; c < 16; c++) {
        if (c < 15) asm volatile("cp.async.wait_group 1;" ::: "memory");
        else        asm volatile("cp.async.wait_group 0;" ::: "memory");
        __syncthreads();

        const unsigned* sIn = sm + (c & 1) * BUF_W;
        const unsigned* sW  = sIn + SIN_W;

#pragma unroll
        for (int tap = 0; tap < 9; tap++) {
            const int dy = tap / 3, dx = tap - 3 * (tap / 3);
            uint2 A0[2], A1[2];
#pragma unroll
            for (int s = 0; s < 2; s++) {
                const unsigned* p0 = sIn + ((2 * mw + s + dy) * 18 + gID + dx) * 8 + 2 * tq;
                A0[s] = *(const uint2*)p0;
                A1[s] = *(const uint2*)(p0 + 8 * 8);   // +8 pixels (cols)
            }
#pragma unroll
            for (int nt = 0; nt < 8; nt++) {
                uint2 Bv = *(const uint2*)(sW + ((tap * 128 + nw * 64 + nt * 8 + gID) * 8) + 2 * tq);
                mma16(acc[0][nt], A0[0], A1[0], Bv);
                mma16(acc[1][nt], A0[1], A1[1], Bv);
            }
        }
        __syncthreads();
        if (c + 2 < 16) stage(c + 2, c & 1);
    }

    // ---- epilogue ----
    if (!packed) {
        unsigned* ob = (unsigned*)jb.dst + (long)b * HP * WP * 128;
#pragma unroll
        for (int s = 0; s < 2; s++) {
            int y = y0 + 2 * mw + s;
            long rowb = (long)(y + 1) * WP * 128;
#pragma unroll
            for (int nt = 0; nt < 8; nt++) {
                int co = coB + nw * 64 + nt * 8 + (tq << 1);
                int p  = co >> 1;
                int wrd = (p >> 3) * 8 + slot_of(p & 7);
                float b0 = jb.bias[co], b1 = jb.bias[co + 1];
                float4 a = acc[s][nt];
                float v0 = a.x + b0, v1 = a.y + b1, v2 = a.z + b0, v3 = a.w + b1;
                if (relu) {
                    v0 = fmaxf(v0, 0.f); v1 = fmaxf(v1, 0.f);
                    v2 = fmaxf(v2, 0.f); v3 = fmaxf(v3, 0.f);
                }
                ob[rowb + (long)(x0 + gID + 1) * 128 + wrd] = pk(v0, v1);
                ob[rowb + (long)(x0 + gID + 9) * 128 + wrd] = pk(v2, v3);
            }
        }
    } else {
        float* out = (float*)jb.dst;
#pragma unroll
        for (int s = 0; s < 2; s++) {
            int y = y0 + 2 * mw + s;
            long base  = ((long)b * TOTLOC + jb.loc_off + (long)y * W + x0 + gID) * CHTOT + jb.ch_off;
            long base8 = base + 8L * CHTOT;
#pragma unroll
            for (int nt = 0; nt < 8; nt++) {
                int co = coB + nw * 64 + nt * 8 + (tq << 1);
                if (co < Cout) {
                    float bv = jb.bias[co];
                    float4 a = acc[s][nt];
                    out[base  + co] = a.x + bv;
                    out[base8 + co] = a.z + bv;
                    if (co + 1 < Cout) {
                        float bv1 = jb.bias[co + 1];
                        out[base  + co + 1] = a.y + bv1;
                        out[base8 + co + 1] = a.w + bv1;
                    }
                }
            }
        }
    }
}

// ---------------------------------------------------------------------------
// lateral 1x1: NCHW fp32 -> padded NHWC bf16 words (slot-permuted)
// ---------------------------------------------------------------------------
__global__ __launch_bounds__(256)
void lat_k(const float* __restrict__ in, const float* __restrict__ w,
           const float* __restrict__ bias, unsigned* __restrict__ out,
           int Cin, int H, int W)
{
    int HW = H * W;
    int idx = blockIdx.x * 256 + threadIdx.x;
    int total = B * 64 * HW;
    if (idx >= total) return;
    int px = idx % HW;
    int t  = idx / HW;
    int cg = t % 64;
    int b  = t / 64;
    int co = cg * 4;
    float a0 = bias[co], a1 = bias[co + 1], a2 = bias[co + 2], a3 = bias[co + 3];
    const float* ip = in + (long)b * Cin * HW + px;
    const float* w0 = w + (long)(co + 0) * Cin;
    const float* w1 = w + (long)(co + 1) * Cin;
    const float* w2 = w + (long)(co + 2) * Cin;
    const float* w3 = w + (long)(co + 3) * Cin;
    for (int ci = 0; ci < Cin; ci++) {
        float v = ip[(long)ci * HW];
        a0 += w0[ci] * v; a1 += w1[ci] * v; a2 += w2[ci] * v; a3 += w3[ci] * v;
    }
    int y = px / W, x = px % W;
    unsigned* base = out + ((long)(b * (H + 2) + y + 1) * (W + 2) + x + 1) * 128;
    int p0 = 2 * cg;
    int g  = p0 >> 3;
    base[g * 8 + slot_of(p0 & 7)]       = pk(a0, a1);
    base[g * 8 + slot_of((p0 + 1) & 7)] = pk(a2, a3);
}

// dst += nearest-up2(src), bf16x2 words, identical layouts
__global__ __launch_bounds__(256)
void upadd_k(unsigned* __restrict__ dst, const unsigned* __restrict__ src, int H, int W)
{
    long idx = (long)blockIdx.x * 256 + threadIdx.x;
    long total = (long)B * H * W * 128;
    if (idx >= total) return;
    int wrd = idx & 127;
    long p = idx >> 7;
    int x = p % W;
    int y = (p / W) % H;
    int b = p / ((long)W * H);
    unsigned* d = &dst[((long)(b * (H + 2) + y + 1) * (W + 2) + x + 1) * 128 + wrd];
    const unsigned* s = &src[((long)(b * (H / 2 + 2) + (y >> 1) + 1) * (W / 2 + 2) + (x >> 1) + 1) * 128 + wrd];
    __nv_bfloat162 dv = *(__nv_bfloat162*)d, sv = *(const __nv_bfloat162*)s;
    *d = pk(__bfloat162float(dv.x) + __bfloat162float(sv.x),
            __bfloat162float(dv.y) + __bfloat162float(sv.y));
}

__global__ void zero_k(float4* p, long n4)
{
    long i = (long)blockIdx.x * blockDim.x + threadIdx.x;
    long stride = (long)gridDim.x * blockDim.x;
    for (; i < n4; i += stride) p[i] = make_float4(0.f, 0.f, 0.f, 0.f);
}

// OIHW fp32 [256][256][9] -> bf16 words [g][tap][256][slot8], 11 jobs fused
struct Srcs { const float* s[11]; };
__global__ void xform11_k(Srcs ss, unsigned* __restrict__ dst)
{
    int j = blockIdx.y;
    long idx = (long)blockIdx.x * 256 + threadIdx.x;   // 0 .. 9*128*256-1
    int co = idx % 256;
    long r = idx / 256;
    int p = r % 128;
    int tap = r / 128;
    int g = p >> 3, w = p & 7;
    int ci = 2 * p;
    const float* src = ss.s[j];
    float f0 = src[(long)co * 2304 + ci * 9 + tap];
    float f1 = src[(long)co * 2304 + (ci + 1) * 9 + tap];
    dst[(long)j * W256 + (((long)(g * 9 + tap) * 256) + co) * 8 + slot_of(w)] = pk(f0, f1);
}

// small-conv variant (CoutPad 128, column offset)
__global__ void transform_k(const float* __restrict__ src, unsigned* __restrict__ dst,
                            int CoutSrc, int CoutPad, int coOff)
{
    long idx = (long)blockIdx.x * blockDim.x + threadIdx.x;
    long total = 9L * 128 * CoutSrc;
    if (idx >= total) return;
    int co = idx % CoutSrc;
    long r = idx / CoutSrc;
    int p = r % 128;
    int tap = r / 128;
    int g = p >> 3, w = p & 7;
    int ci = 2 * p;
    float f0 = src[(long)co * 2304 + ci * 9 + tap];
    float f1 = src[(long)co * 2304 + (ci + 1) * 9 + tap];
    dst[(((long)(g * 9 + tap) * CoutPad) + coOff + co) * 8 + slot_of(w)] = pk(f0, f1);
}

__global__ void biasbc_k(const float* bb, const float* tb, float* dst)
{
    int i = threadIdx.x;
    if (i < 4) dst[i] = bb[i];
    else if (i == 4) dst[i] = tb[0];
}

// ---------------------------------------------------------------------------
extern "C" void kernel_launch(void* const* d_in, const int* in_sizes, int n_in,
                              void* d_out, int out_size)
{
    auto idxOf = [&](int sz, int ord) -> int {
        int c = 0;
        for (int i = 0; i < n_in; i++)
            if (in_sizes[i] == sz) { if (c == ord) return i; c++; }
        return -1;
    };
    const int i_c3  = idxOf(2 * 64 * 64 * 64, 0);
    const int i_c4  = idxOf(2 * 160 * 32 * 32, 0);
    const int i_c5  = idxOf(2 * 400 * 16 * 16, 0);
    const int i_l3w = idxOf(256 * 64, 0);
    const int i_l4w = idxOf(256 * 160, 0);
    const int i_l5w = idxOf(256 * 400, 0);
    const int i_o3w = idxOf(256 * 256 * 9, 0);
    const int i_o4w = idxOf(256 * 256 * 9, 1);
    const int i_o5w = idxOf(256 * 256 * 9, 2);
    const int i_scw = idxOf(4 * 256 * 256 * 9, 0);
    const int i_sbw = idxOf(4 * 256 * 256 * 9, 1);
    const int i_cw  = idxOf(80 * 256 * 9, 0);
    const int i_bw  = idxOf(4 * 256 * 9, 0);
    const int i_tw  = idxOf(1 * 256 * 9, 0);

    const float* c3 = (const float*)d_in[i_c3];
    const float* c4 = (const float*)d_in[i_c4];
    const float* c5 = (const float*)d_in[i_c5];
    const float* l3w = (const float*)d_in[i_l3w]; const float* l3b = (const float*)d_in[i_l3w + 1];
    const float* l4w = (const float*)d_in[i_l4w]; const float* l4b = (const float*)d_in[i_l4w + 1];
    const float* l5w = (const float*)d_in[i_l5w]; const float* l5b = (const float*)d_in[i_l5w + 1];
    const float* o3w = (const float*)d_in[i_o3w]; const float* o3b = (const float*)d_in[i_o3w + 1];
    const float* o4w = (const float*)d_in[i_o4w]; const float* o4b = (const float*)d_in[i_o4w + 1];
    const float* o5w = (const float*)d_in[i_o5w]; const float* o5b = (const float*)d_in[i_o5w + 1];
    const float* scw = (const float*)d_in[i_scw]; const float* scb = (const float*)d_in[i_scw + 1];
    const float* sbw = (const float*)d_in[i_sbw]; const float* sbb = (const float*)d_in[i_sbw + 1];
    const float* cw  = (const float*)d_in[i_cw];  const float* cb  = (const float*)d_in[i_cw + 1];
    const float* bw  = (const float*)d_in[i_bw];  const float* bb  = (const float*)d_in[i_bw + 1];
    const float* tw  = (const float*)d_in[i_tw];  const float* tb  = (const float*)d_in[i_tw + 1];

    unsigned *act, *wt, *wt_cls, *wt_bc;
    float* bias_bc;
    cudaGetSymbolAddress((void**)&act, g_act);
    cudaGetSymbolAddress((void**)&wt, g_wt);
    cudaGetSymbolAddress((void**)&wt_cls, g_wt_cls);
    cudaGetSymbolAddress((void**)&wt_bc, g_wt_bc);
    cudaGetSymbolAddress((void**)&bias_bc, g_bias_bc);

    // buffer carve per level: 0=lat, 1=p, 2=tA, 3=tB, 4=tC, 5=tD
    unsigned* L3p[6]; unsigned* L4p[6]; unsigned* L5p[6];
    for (int i = 0; i < 6; i++) L3p[i] = act + (long)i * S3W;
    unsigned* b4 = act + 6L * S3W;
    for (int i = 0; i < 6; i++) L4p[i] = b4 + (long)i * S4W;
    unsigned* b5 = b4 + 6L * S4W;
    for (int i = 0; i < 6; i++) L5p[i] = b5 + (long)i * S5W;

    cudaFuncSetAttribute(conv_tc_k, cudaFuncAttributeMaxDynamicSharedMemorySize, SMEM_BYTES);

    float* out = (float*)d_out;

    // ---- zero activation pool (borders must stay 0) + padded small weights ----
    zero_k<<<512, 256>>>((float4*)act, (long)(6L * S3W + 6L * S4W + 6L * S5W) / 4);
    zero_k<<<64, 256>>>((float4*)wt_cls, W128 / 4);
    zero_k<<<64, 256>>>((float4*)wt_bc,  W128 / 4);

    // ---- weight transforms (fused 11-way + 3 small) ----
    {
        Srcs ss;
        ss.s[0] = o3w; ss.s[1] = o4w; ss.s[2] = o5w;
        for (int i = 0; i < 4; i++) {
            ss.s[3 + i] = scw + (long)i * 256 * 256 * 9;
            ss.s[7 + i] = sbw + (long)i * 256 * 256 * 9;
        }
        dim3 g((unsigned)((9L * 128 * 256 + 255) / 256), 11);
        xform11_k<<<g, 256>>>(ss, wt);
        long totc = 9L * 128 * 80;
        transform_k<<<(int)((totc + 255) / 256), 256>>>(cw, wt_cls, 80, 128, 0);
        long totb = 9L * 128 * 4;
        transform_k<<<(int)((totb + 255) / 256), 256>>>(bw, wt_bc, 4, 128, 0);
        long tott = 9L * 128 * 1;
        transform_k<<<(int)((tott + 255) / 256), 256>>>(tw, wt_bc, 1, 128, 4);
        biasbc_k<<<1, 8>>>(bb, tb, bias_bc);
    }

    // ---- FPN laterals ----
    lat_k<<<(B * 64 * 256 + 255) / 256, 256>>>(c5, l5w, l5b, L5p[0], 400, 16, 16);
    lat_k<<<(B * 64 * 1024 + 255) / 256, 256>>>(c4, l4w, l4b, L4p[0], 160, 32, 32);
    lat_k<<<(B * 64 * 4096 + 255) / 256, 256>>>(c3, l3w, l3b, L3p[0], 64, 64, 64);

    const int nT[3] = { 32, 8, 2 };
    const int Hs[3] = { 64, 32, 16 }, Ws[3] = { 64, 32, 16 };
    const int locs[3] = { 0, 4096, 5120 };

    auto mkJob = [&](const unsigned* src, const unsigned* w, const float* bias,
                     void* dst, int L, int start, int nCoB, int Cout, int flags,
                     int loc, int ch) {
        Job j;
        j.src = src; j.wgt = w; j.bias = bias; j.dst = dst;
        j.H = Hs[L]; j.W = Ws[L]; j.start = start; j.nCoB = nCoB;
        j.Cout = Cout; j.flags = flags; j.loc_off = loc; j.ch_off = ch;
        return j;
    };

    // ---- FPN 3x3 out convs (serial: p5 -> upadd -> p4 -> upadd -> p3) ----
    {
        JobSet js; js.nj = 1;
        js.j[0] = mkJob(L5p[0], wt + 2L * W256, o5b, L5p[1], 2, 0, 2, 256, 0, 0, 0);
        conv_tc_k<<<nT[2] * 4, 256, SMEM_BYTES>>>(js);
        long n = (long)B * 32 * 32 * 128;
        upadd_k<<<(int)((n + 255) / 256), 256>>>(L4p[0], L5p[0], 32, 32);
        js.j[0] = mkJob(L4p[0], wt + 1L * W256, o4b, L4p[1], 1, 0, 2, 256, 0, 0, 0);
        conv_tc_k<<<nT[1] * 4, 256, SMEM_BYTES>>>(js);
        n = (long)B * 64 * 64 * 128;
        upadd_k<<<(int)((n + 255) / 256), 256>>>(L3p[0], L4p[0], 64, 64);
        js.j[0] = mkJob(L3p[0], wt + 0L * W256, o3b, L3p[1], 0, 0, 2, 256, 0, 0, 0);
        conv_tc_k<<<nT[0] * 4, 256, SMEM_BYTES>>>(js);
    }

    // ---- fused stems: 4 launches, each = 3 levels x 2 branches (336 CTAs) ----
    unsigned** Lp[3] = { L3p, L4p, L5p };
    for (int i = 0; i < 4; i++) {
        int sc_s = (i == 0) ? 1 : ((i & 1) ? 2 : 3);
        int sc_d = (i & 1) ? 3 : 2;
        int sb_s = (i == 0) ? 1 : ((i & 1) ? 4 : 5);
        int sb_d = (i & 1) ? 5 : 4;
        JobSet js; js.nj = 6;
        int start = 0;
        for (int L = 0; L < 3; L++) {
            js.j[2 * L] = mkJob(Lp[L][sc_s], wt + (3 + i) * (long)W256, scb + i * 256,
                                Lp[L][sc_d], L, start, 2, 256, 1, 0, 0);
            start += nT[L] * 4;
            js.j[2 * L + 1] = mkJob(Lp[L][sb_s], wt + (7 + i) * (long)W256, sbb + i * 256,
                                    Lp[L][sb_d], L, start, 2, 256, 1, 0, 0);
            start += nT[L] * 4;
        }
        conv_tc_k<<<start, 256, SMEM_BYTES>>>(js);
    }

    // ---- fused finals: cls (from tB=3) + box/ctr (from tD=5), 168 CTAs ----
    {
        JobSet js; js.nj = 6;
        int start = 0;
        for (int L = 0; L < 3; L++) {
            js.j[L] = mkJob(Lp[L][3], wt_cls, cb, out, L, start, 1, NUMC, 2, locs[L], 0);
            start += nT[L] * 2;
        }
        for (int L = 0; L < 3; L++) {
            js.j[3 + L] = mkJob(Lp[L][5], wt_bc, bias_bc, out, L, start, 1, 5, 2, locs[L], 80);
            start += nT[L] * 2;
        }
        conv_tc_k<<<start, 256, SMEM_BYTES>>>(js);
    }
    (void)out_size;
}

// round 15
// speedup vs baseline: 8.5622x; 1.0454x over previous
#include <cuda_runtime.h>
#include <cuda_bf16.h>
#include <cstdint>

// ---------------------------------------------------------------------------
// FCOS head on GB300 — round 15: R14 conv (bf16 mma.sync, 2 CTAs/SM, fused
// jobs) + single coalesced weight-transform kernel; setup launches minimized
// so ncu -s 5 captures the first conv launch.
// ---------------------------------------------------------------------------

#define NUMC 80
#define CHTOT 85
#define TOTLOC 5376
#define B 2

// ---- activation pool: padded NHWC bf16x2 words, slot-permuted, 6 bufs/level
#define S3W (2 * 66 * 66 * 128)
#define S4W (2 * 34 * 34 * 128)
#define S5W (2 * 18 * 18 * 128)
__device__ unsigned g_act[6 * S3W + 6 * S4W + 6 * S5W];

// ---- transformed bf16 weights: [group16][tap9][coutPad][8 words], permuted
#define W256 (16 * 9 * 256 * 8)
#define W128 (16 * 9 * 128 * 8)
__device__ __align__(16) unsigned g_wt[11 * W256];   // out3/4/5, stem_cls0-3, stem_box0-3
__device__ __align__(16) unsigned g_wt_cls[W128];    // cls, pad 128
__device__ __align__(16) unsigned g_wt_bc [W128];    // box(4)+ctr(1), pad 128
__device__ float g_bias_bc[5];

__device__ __forceinline__ unsigned pk(float a, float b) {
    __nv_bfloat162 h = __floats2bfloat162_rn(a, b);
    return *(unsigned*)&h;
}
__device__ __forceinline__ int slot_of(int w) { return ((w & 3) << 1) | (w >> 2); }

__device__ __forceinline__ void cpa16(void* smem, const void* g) {
    unsigned s = (unsigned)__cvta_generic_to_shared(smem);
    asm volatile("cp.async.cg.shared.global [%0], [%1], 16;" :: "r"(s), "l"(g) : "memory");
}

__device__ __forceinline__ void mma16(float4& d, uint2 A0, uint2 A1, uint2 Bv) {
    asm volatile(
        "mma.sync.aligned.m16n8k16.row.col.f32.bf16.bf16.f32 "
        "{%0,%1,%2,%3}, {%4,%5,%6,%7}, {%8,%9}, {%0,%1,%2,%3};\n"
        : "+f"(d.x), "+f"(d.y), "+f"(d.z), "+f"(d.w)
        : "r"(A0.x), "r"(A1.x), "r"(A0.y), "r"(A1.y),
          "r"(Bv.x), "r"(Bv.y));
}

// ---------------------------------------------------------------------------
// bf16 tensor-core 3x3 conv, multi-job dispatch, 8-word smem stride.
// CTA: 128 pixels (8r x 16c) x 128 couts; 8 warps = 4m x 2n; 16 K-chunks of
// 16 cin, cp.async double-buffered.  flags: 1=relu, 2=packed output.
// ---------------------------------------------------------------------------
#define SIN_W (180 * 8)
#define SW_W  (9 * 128 * 8)
#define BUF_W (SIN_W + SW_W)
#define SMEM_BYTES (2 * BUF_W * 4)       // 85,248 bytes -> 2 CTAs/SM

struct Job {
    const unsigned* src;
    const unsigned* wgt;
    const float* bias;
    void* dst;
    int H, W, start, nCoB, Cout, flags, loc_off, ch_off;
};
struct JobSet { Job j[6]; int nj; };

__global__ __launch_bounds__(256, 2)
void conv_tc_k(JobSet js)
{
    extern __shared__ unsigned sm[];

    int ji = 0;
    for (int k = 1; k < js.nj; k++)
        if ((int)blockIdx.x >= js.j[k].start) ji = k;
    const Job jb = js.j[ji];
    const int H = jb.H, W = jb.W;
    const int Cout = jb.Cout, CoutPad = jb.nCoB << 7;
    const int relu = jb.flags & 1, packed = jb.flags & 2;

    const int local = blockIdx.x - jb.start;
    const int nT = (W >> 4) * (H >> 3);
    const int t = local % nT;
    const int rest = local / nT;
    const int coB = (rest % jb.nCoB) << 7;
    const int b = rest / jb.nCoB;

    const int tid = threadIdx.x, lane = tid & 31, wrp = tid >> 5;
    const int mw = wrp >> 1, nw = wrp & 1, gID = lane >> 2, tq = lane & 3;
    const int tilesX = W >> 4;
    const int x0 = (t % tilesX) << 4;
    const int y0 = (t / tilesX) << 3;
    const int HP = H + 2, WP = W + 2;

    const unsigned* inB = jb.src + (long)b * HP * WP * 128;

    float4 acc[2][8];
#pragma unroll
    for (int s = 0; s < 2; s++)
#pragma unroll
        for (int nt = 0; nt < 8; nt++) acc[s][nt] = make_float4(0.f, 0.f, 0.f, 0.f);

    auto stage = [&](int g, int buf) {
        unsigned* sIn = sm + buf * BUF_W;
        unsigned* sW  = sIn + SIN_W;
        for (int i = tid; i < 360; i += 256) {
            int pix = i >> 1, half = i & 1;
            int rw = pix / 18, cl = pix - rw * 18;
            const unsigned* src = inB + ((long)(y0 + rw) * WP + (x0 + cl)) * 128 + g * 8 + half * 4;
            cpa16(&sIn[pix * 8 + half * 4], src);
        }
        for (int i = tid; i < 2304; i += 256) {
            int half = i & 1;
            int n    = (i >> 1) & 127;
            int tap  = i >> 8;
            const unsigned* src = jb.wgt + (((long)(g * 9 + tap) * CoutPad) + coB + n) * 8 + half * 4;
            cpa16(&sW[(tap * 128 + n) * 8 + half * 4], src);
        }
        asm volatile("cp.async.commit_group;" ::: "memory");
    };

    stage(0, 0);
    stage(1, 1);

    for (int c = 0; c < 16; c++) {
        if (c < 15) asm volatile("cp.async.wait_group 1;" ::: "memory");
        else        asm volatile("cp.async.wait_group 0;" ::: "memory");
        __syncthreads();

        const unsigned* sIn = sm + (c & 1) * BUF_W;
        const unsigned* sW  = sIn + SIN_W;

#pragma unroll
        for (int tap = 0; tap < 9; tap++) {
            const int dy = tap / 3, dx = tap - 3 * (tap / 3);
            uint2 A0[2], A1[2];
#pragma unroll
            for (int s = 0; s < 2; s++) {
                const unsigned* p0 = sIn + ((2 * mw + s + dy) * 18 + gID + dx) * 8 + 2 * tq;
                A0[s] = *(const uint2*)p0;
                A1[s] = *(const uint2*)(p0 + 8 * 8);
            }
#pragma unroll
            for (int nt = 0; nt < 8; nt++) {
                uint2 Bv = *(const uint2*)(sW + ((tap * 128 + nw * 64 + nt * 8 + gID) * 8) + 2 * tq);
                mma16(acc[0][nt], A0[0], A1[0], Bv);
                mma16(acc[1][nt], A0[1], A1[1], Bv);
            }
        }
        __syncthreads();
        if (c + 2 < 16) stage(c + 2, c & 1);
    }

    // ---- epilogue ----
    if (!packed) {
        unsigned* ob = (unsigned*)jb.dst + (long)b * HP * WP * 128;
#pragma unroll
        for (int s = 0; s < 2; s++) {
            int y = y0 + 2 * mw + s;
            long rowb = (long)(y + 1) * WP * 128;
#pragma unroll
            for (int nt = 0; nt < 8; nt++) {
                int co = coB + nw * 64 + nt * 8 + (tq << 1);
                int p  = co >> 1;
                int wrd = (p >> 3) * 8 + slot_of(p & 7);
                float b0 = jb.bias[co], b1 = jb.bias[co + 1];
                float4 a = acc[s][nt];
                float v0 = a.x + b0, v1 = a.y + b1, v2 = a.z + b0, v3 = a.w + b1;
                if (relu) {
                    v0 = fmaxf(v0, 0.f); v1 = fmaxf(v1, 0.f);
                    v2 = fmaxf(v2, 0.f); v3 = fmaxf(v3, 0.f);
                }
                ob[rowb + (long)(x0 + gID + 1) * 128 + wrd] = pk(v0, v1);
                ob[rowb + (long)(x0 + gID + 9) * 128 + wrd] = pk(v2, v3);
            }
        }
    } else {
        float* out = (float*)jb.dst;
#pragma unroll
        for (int s = 0; s < 2; s++) {
            int y = y0 + 2 * mw + s;
            long base  = ((long)b * TOTLOC + jb.loc_off + (long)y * W + x0 + gID) * CHTOT + jb.ch_off;
            long base8 = base + 8L * CHTOT;
#pragma unroll
            for (int nt = 0; nt < 8; nt++) {
                int co = coB + nw * 64 + nt * 8 + (tq << 1);
                if (co < Cout) {
                    float bv = jb.bias[co];
                    float4 a = acc[s][nt];
                    out[base  + co] = a.x + bv;
                    out[base8 + co] = a.z + bv;
                    if (co + 1 < Cout) {
                        float bv1 = jb.bias[co + 1];
                        out[base  + co + 1] = a.y + bv1;
                        out[base8 + co + 1] = a.w + bv1;
                    }
                }
            }
        }
    }
}

// ---------------------------------------------------------------------------
// lateral 1x1: NCHW fp32 -> padded NHWC bf16 words (slot-permuted)
// ---------------------------------------------------------------------------
__global__ __launch_bounds__(256)
void lat_k(const float* __restrict__ in, const float* __restrict__ w,
           const float* __restrict__ bias, unsigned* __restrict__ out,
           int Cin, int H, int W)
{
    int HW = H * W;
    int idx = blockIdx.x * 256 + threadIdx.x;
    int total = B * 64 * HW;
    if (idx >= total) return;
    int px = idx % HW;
    int t  = idx / HW;
    int cg = t % 64;
    int b  = t / 64;
    int co = cg * 4;
    float a0 = bias[co], a1 = bias[co + 1], a2 = bias[co + 2], a3 = bias[co + 3];
    const float* ip = in + (long)b * Cin * HW + px;
    const float* w0 = w + (long)(co + 0) * Cin;
    const float* w1 = w + (long)(co + 1) * Cin;
    const float* w2 = w + (long)(co + 2) * Cin;
    const float* w3 = w + (long)(co + 3) * Cin;
    for (int ci = 0; ci < Cin; ci++) {
        float v = ip[(long)ci * HW];
        a0 += w0[ci] * v; a1 += w1[ci] * v; a2 += w2[ci] * v; a3 += w3[ci] * v;
    }
    int y = px / W, x = px % W;
    unsigned* base = out + ((long)(b * (H + 2) + y + 1) * (W + 2) + x + 1) * 128;
    int p0 = 2 * cg;
    int g  = p0 >> 3;
    base[g * 8 + slot_of(p0 & 7)]       = pk(a0, a1);
    base[g * 8 + slot_of((p0 + 1) & 7)] = pk(a2, a3);
}

// dst += nearest-up2(src), bf16x2 words, identical layouts
__global__ __launch_bounds__(256)
void upadd_k(unsigned* __restrict__ dst, const unsigned* __restrict__ src, int H, int W)
{
    long idx = (long)blockIdx.x * 256 + threadIdx.x;
    long total = (long)B * H * W * 128;
    if (idx >= total) return;
    int wrd = idx & 127;
    long p = idx >> 7;
    int x = p % W;
    int y = (p / W) % H;
    int b = p / ((long)W * H);
    unsigned* d = &dst[((long)(b * (H + 2) + y + 1) * (W + 2) + x + 1) * 128 + wrd];
    const unsigned* s = &src[((long)(b * (H / 2 + 2) + (y >> 1) + 1) * (W / 2 + 2) + (x >> 1) + 1) * 128 + wrd];
    __nv_bfloat162 dv = *(__nv_bfloat162*)d, sv = *(const __nv_bfloat162*)s;
    *d = pk(__bfloat162float(dv.x) + __bfloat162float(sv.x),
            __bfloat162float(dv.y) + __bfloat162float(sv.y));
}

__global__ void zero_k(float4* p, long n4)
{
    long i = (long)blockIdx.x * blockDim.x + threadIdx.x;
    long stride = (long)gridDim.x * blockDim.x;
    for (; i < n4; i += stride) p[i] = make_float4(0.f, 0.f, 0.f, 0.f);
}

// ---------------------------------------------------------------------------
// Fused, coalesced weight transform. Block = (job j, cout co).
// Reads the cout's 2304 fp32 weights contiguously into smem, emits 144
// 32-byte chunks [g*9+tap][co][8 slots]. Jobs 11 (cls) / 12 (box+ctr) are
// zero-padded to 128 couts; job 12 also writes g_bias_bc.
// ---------------------------------------------------------------------------
struct XJobs { const float* s[14]; const float* bb; const float* tb; };

__global__ __launch_bounds__(256)
void xform13_k(XJobs xj, unsigned* __restrict__ wt, unsigned* __restrict__ wt_cls,
               unsigned* __restrict__ wt_bc, float* __restrict__ bias_bc)
{
    __shared__ float w[2304];
    const int j = blockIdx.y;
    const int co = blockIdx.x;
    const int CoutPad = (j < 11) ? 256 : 128;
    if (co >= CoutPad) return;
    const int tid = threadIdx.x;

    unsigned* dst = (j < 11) ? (wt + (long)j * W256) : (j == 11 ? wt_cls : wt_bc);

    const float* srcRow = nullptr;
    if (j < 11)       srcRow = xj.s[j] + (long)co * 2304;
    else if (j == 11) { if (co < 80) srcRow = xj.s[11] + (long)co * 2304; }
    else {
        if (co < 4)       srcRow = xj.s[12] + (long)co * 2304;
        else if (co == 4) srcRow = xj.s[13];
        if (co == 0 && tid < 5)
            bias_bc[tid] = (tid < 4) ? xj.bb[tid] : xj.tb[0];
    }

    if (srcRow)
        for (int i = tid; i < 2304; i += 256) w[i] = srcRow[i];
    __syncthreads();

    if (tid < 144) {
        const int g = tid / 9, tap = tid - 9 * (tid / 9);
        unsigned wd[8];
        if (srcRow) {
#pragma unroll
            for (int v = 0; v < 8; v++) {
                int ci = 16 * g + 2 * v;
                wd[slot_of(v)] = pk(w[ci * 9 + tap], w[(ci + 1) * 9 + tap]);
            }
        } else {
#pragma unroll
            for (int v = 0; v < 8; v++) wd[v] = 0u;
        }
        unsigned* o = dst + (((long)(g * 9 + tap)) * CoutPad + co) * 8;
        *(uint4*)o       = make_uint4(wd[0], wd[1], wd[2], wd[3]);
        *(uint4*)(o + 4) = make_uint4(wd[4], wd[5], wd[6], wd[7]);
    }
}

// ---------------------------------------------------------------------------
extern "C" void kernel_launch(void* const* d_in, const int* in_sizes, int n_in,
                              void* d_out, int out_size)
{
    auto idxOf = [&](int sz, int ord) -> int {
        int c = 0;
        for (int i = 0; i < n_in; i++)
            if (in_sizes[i] == sz) { if (c == ord) return i; c++; }
        return -1;
    };
    const int i_c3  = idxOf(2 * 64 * 64 * 64, 0);
    const int i_c4  = idxOf(2 * 160 * 32 * 32, 0);
    const int i_c5  = idxOf(2 * 400 * 16 * 16, 0);
    const int i_l3w = idxOf(256 * 64, 0);
    const int i_l4w = idxOf(256 * 160, 0);
    const int i_l5w = idxOf(256 * 400, 0);
    const int i_o3w = idxOf(256 * 256 * 9, 0);
    const int i_o4w = idxOf(256 * 256 * 9, 1);
    const int i_o5w = idxOf(256 * 256 * 9, 2);
    const int i_scw = idxOf(4 * 256 * 256 * 9, 0);
    const int i_sbw = idxOf(4 * 256 * 256 * 9, 1);
    const int i_cw  = idxOf(80 * 256 * 9, 0);
    const int i_bw  = idxOf(4 * 256 * 9, 0);
    const int i_tw  = idxOf(1 * 256 * 9, 0);

    const float* c3 = (const float*)d_in[i_c3];
    const float* c4 = (const float*)d_in[i_c4];
    const float* c5 = (const float*)d_in[i_c5];
    const float* l3w = (const float*)d_in[i_l3w]; const float* l3b = (const float*)d_in[i_l3w + 1];
    const float* l4w = (const float*)d_in[i_l4w]; const float* l4b = (const float*)d_in[i_l4w + 1];
    const float* l5w = (const float*)d_in[i_l5w]; const float* l5b = (const float*)d_in[i_l5w + 1];
    const float* o3w = (const float*)d_in[i_o3w]; const float* o3b = (const float*)d_in[i_o3w + 1];
    const float* o4w = (const float*)d_in[i_o4w]; const float* o4b = (const float*)d_in[i_o4w + 1];
    const float* o5w = (const float*)d_in[i_o5w]; const float* o5b = (const float*)d_in[i_o5w + 1];
    const float* scw = (const float*)d_in[i_scw]; const float* scb = (const float*)d_in[i_scw + 1];
    const float* sbw = (const float*)d_in[i_sbw]; const float* sbb = (const float*)d_in[i_sbw + 1];
    const float* cw  = (const float*)d_in[i_cw];  const float* cb  = (const float*)d_in[i_cw + 1];
    const float* bw  = (const float*)d_in[i_bw];  const float* bb  = (const float*)d_in[i_bw + 1];
    const float* tw  = (const float*)d_in[i_tw];  const float* tb  = (const float*)d_in[i_tw + 1];

    unsigned *act, *wt, *wt_cls, *wt_bc;
    float* bias_bc;
    cudaGetSymbolAddress((void**)&act, g_act);
    cudaGetSymbolAddress((void**)&wt, g_wt);
    cudaGetSymbolAddress((void**)&wt_cls, g_wt_cls);
    cudaGetSymbolAddress((void**)&wt_bc, g_wt_bc);
    cudaGetSymbolAddress((void**)&bias_bc, g_bias_bc);

    // buffer carve per level: 0=lat, 1=p, 2=tA, 3=tB, 4=tC, 5=tD
    unsigned* L3p[6]; unsigned* L4p[6]; unsigned* L5p[6];
    for (int i = 0; i < 6; i++) L3p[i] = act + (long)i * S3W;
    unsigned* b4 = act + 6L * S3W;
    for (int i = 0; i < 6; i++) L4p[i] = b4 + (long)i * S4W;
    unsigned* b5 = b4 + 6L * S4W;
    for (int i = 0; i < 6; i++) L5p[i] = b5 + (long)i * S5W;

    cudaFuncSetAttribute(conv_tc_k, cudaFuncAttributeMaxDynamicSharedMemorySize, SMEM_BYTES);

    float* out = (float*)d_out;

    // launch 0: zero activation pool (borders must stay 0)
    zero_k<<<512, 256>>>((float4*)act, (long)(6L * S3W + 6L * S4W + 6L * S5W) / 4);

    // launch 1: all weight transforms + bias_bc, fused & coalesced
    {
        XJobs xj;
        xj.s[0] = o3w; xj.s[1] = o4w; xj.s[2] = o5w;
        for (int i = 0; i < 4; i++) {
            xj.s[3 + i] = scw + (long)i * 256 * 256 * 9;
            xj.s[7 + i] = sbw + (long)i * 256 * 256 * 9;
        }
        xj.s[11] = cw; xj.s[12] = bw; xj.s[13] = tw;
        xj.bb = bb; xj.tb = tb;
        xform13_k<<<dim3(256, 13), 256>>>(xj, wt, wt_cls, wt_bc, bias_bc);
    }

    // launches 2-4: FPN laterals
    lat_k<<<(B * 64 * 256 + 255) / 256, 256>>>(c5, l5w, l5b, L5p[0], 400, 16, 16);
    lat_k<<<(B * 64 * 1024 + 255) / 256, 256>>>(c4, l4w, l4b, L4p[0], 160, 32, 32);
    lat_k<<<(B * 64 * 4096 + 255) / 256, 256>>>(c3, l3w, l3b, L3p[0], 64, 64, 64);

    const int nT[3] = { 32, 8, 2 };
    const int Hs[3] = { 64, 32, 16 }, Ws[3] = { 64, 32, 16 };
    const int locs[3] = { 0, 4096, 5120 };

    auto mkJob = [&](const unsigned* src, const unsigned* w, const float* bias,
                     void* dst, int L, int start, int nCoB, int Cout, int flags,
                     int loc, int ch) {
        Job j;
        j.src = src; j.wgt = w; j.bias = bias; j.dst = dst;
        j.H = Hs[L]; j.W = Ws[L]; j.start = start; j.nCoB = nCoB;
        j.Cout = Cout; j.flags = flags; j.loc_off = loc; j.ch_off = ch;
        return j;
    };

    // ---- FPN 3x3 out convs (serial: p5 -> upadd -> p4 -> upadd -> p3) ----
    {
        JobSet js; js.nj = 1;
        js.j[0] = mkJob(L5p[0], wt + 2L * W256, o5b, L5p[1], 2, 0, 2, 256, 0, 0, 0);
        conv_tc_k<<<nT[2] * 4, 256, SMEM_BYTES>>>(js);     // launch 5 (ncu target)
        long n = (long)B * 32 * 32 * 128;
        upadd_k<<<(int)((n + 255) / 256), 256>>>(L4p[0], L5p[0], 32, 32);
        js.j[0] = mkJob(L4p[0], wt + 1L * W256, o4b, L4p[1], 1, 0, 2, 256, 0, 0, 0);
        conv_tc_k<<<nT[1] * 4, 256, SMEM_BYTES>>>(js);
        n = (long)B * 64 * 64 * 128;
        upadd_k<<<(int)((n + 255) / 256), 256>>>(L3p[0], L4p[0], 64, 64);
        js.j[0] = mkJob(L3p[0], wt + 0L * W256, o3b, L3p[1], 0, 0, 2, 256, 0, 0, 0);
        conv_tc_k<<<nT[0] * 4, 256, SMEM_BYTES>>>(js);
    }

    // ---- fused stems: 4 launches, each = 3 levels x 2 branches (336 CTAs) ----
    unsigned** Lp[3] = { L3p, L4p, L5p };
    for (int i = 0; i < 4; i++) {
        int sc_s = (i == 0) ? 1 : ((i & 1) ? 2 : 3);
        int sc_d = (i & 1) ? 3 : 2;
        int sb_s = (i == 0) ? 1 : ((i & 1) ? 4 : 5);
        int sb_d = (i & 1) ? 5 : 4;
        JobSet js; js.nj = 6;
        int start = 0;
        for (int L = 0; L < 3; L++) {
            js.j[2 * L] = mkJob(Lp[L][sc_s], wt + (3 + i) * (long)W256, scb + i * 256,
                                Lp[L][sc_d], L, start, 2, 256, 1, 0, 0);
            start += nT[L] * 4;
            js.j[2 * L + 1] = mkJob(Lp[L][sb_s], wt + (7 + i) * (long)W256, sbb + i * 256,
                                    Lp[L][sb_d], L, start, 2, 256, 1, 0, 0);
            start += nT[L] * 4;
        }
        conv_tc_k<<<start, 256, SMEM_BYTES>>>(js);
    }

    // ---- fused finals: cls (from tB=3) + box/ctr (from tD=5), 168 CTAs ----
    {
        JobSet js; js.nj = 6;
        int start = 0;
        for (int L = 0; L < 3; L++) {
            js.j[L] = mkJob(Lp[L][3], wt_cls, cb, out, L, start, 1, NUMC, 2, locs[L], 0);
            start += nT[L] * 2;
        }
        for (int L = 0; L < 3; L++) {
            js.j[3 + L] = mkJob(Lp[L][5], wt_bc, bias_bc, out, L, start, 1, 5, 2, locs[L], 80);
            start += nT[L] * 2;
        }
        conv_tc_k<<<start, 256, SMEM_BYTES>>>(js);
    }
    (void)out_size;
}

// round 16
// speedup vs baseline: 9.0885x; 1.0615x over previous
#include <cuda_runtime.h>
#include <cuda_bf16.h>
#include <cstdint>

// ---------------------------------------------------------------------------
// FCOS head on GB300 — round 16: R15 + (a) ILP-optimized laterals (4 pix x 4
// couts per thread), (b) all three FPN out-convs fused into ONE launch (they
// are independent once the up-adds — which use laterals only — are done).
// ---------------------------------------------------------------------------

#define NUMC 80
#define CHTOT 85
#define TOTLOC 5376
#define B 2

// ---- activation pool: padded NHWC bf16x2 words, slot-permuted, 6 bufs/level
#define S3W (2 * 66 * 66 * 128)
#define S4W (2 * 34 * 34 * 128)
#define S5W (2 * 18 * 18 * 128)
__device__ unsigned g_act[6 * S3W + 6 * S4W + 6 * S5W];

// ---- transformed bf16 weights: [group16][tap9][coutPad][8 words], permuted
#define W256 (16 * 9 * 256 * 8)
#define W128 (16 * 9 * 128 * 8)
__device__ __align__(16) unsigned g_wt[11 * W256];   // out3/4/5, stem_cls0-3, stem_box0-3
__device__ __align__(16) unsigned g_wt_cls[W128];    // cls, pad 128
__device__ __align__(16) unsigned g_wt_bc [W128];    // box(4)+ctr(1), pad 128
__device__ float g_bias_bc[5];

__device__ __forceinline__ unsigned pk(float a, float b) {
    __nv_bfloat162 h = __floats2bfloat162_rn(a, b);
    return *(unsigned*)&h;
}
__device__ __forceinline__ int slot_of(int w) { return ((w & 3) << 1) | (w >> 2); }

__device__ __forceinline__ void cpa16(void* smem, const void* g) {
    unsigned s = (unsigned)__cvta_generic_to_shared(smem);
    asm volatile("cp.async.cg.shared.global [%0], [%1], 16;" :: "r"(s), "l"(g) : "memory");
}

__device__ __forceinline__ void mma16(float4& d, uint2 A0, uint2 A1, uint2 Bv) {
    asm volatile(
        "mma.sync.aligned.m16n8k16.row.col.f32.bf16.bf16.f32 "
        "{%0,%1,%2,%3}, {%4,%5,%6,%7}, {%8,%9}, {%0,%1,%2,%3};\n"
        : "+f"(d.x), "+f"(d.y), "+f"(d.z), "+f"(d.w)
        : "r"(A0.x), "r"(A1.x), "r"(A0.y), "r"(A1.y),
          "r"(Bv.x), "r"(Bv.y));
}

// ---------------------------------------------------------------------------
// bf16 tensor-core 3x3 conv, multi-job dispatch, 8-word smem stride.
// CTA: 128 pixels (8r x 16c) x 128 couts; 8 warps = 4m x 2n; 16 K-chunks of
// 16 cin, cp.async double-buffered.  flags: 1=relu, 2=packed output.
// ---------------------------------------------------------------------------
#define SIN_W (180 * 8)
#define SW_W  (9 * 128 * 8)
#define BUF_W (SIN_W + SW_W)
#define SMEM_BYTES (2 * BUF_W * 4)       // 85,248 bytes -> 2 CTAs/SM

struct Job {
    const unsigned* src;
    const unsigned* wgt;
    const float* bias;
    void* dst;
    int H, W, start, nCoB, Cout, flags, loc_off, ch_off;
};
struct JobSet { Job j[6]; int nj; };

__global__ __launch_bounds__(256, 2)
void conv_tc_k(JobSet js)
{
    extern __shared__ unsigned sm[];

    int ji = 0;
    for (int k = 1; k < js.nj; k++)
        if ((int)blockIdx.x >= js.j[k].start) ji = k;
    const Job jb = js.j[ji];
    const int H = jb.H, W = jb.W;
    const int Cout = jb.Cout, CoutPad = jb.nCoB << 7;
    const int relu = jb.flags & 1, packed = jb.flags & 2;

    const int local = blockIdx.x - jb.start;
    const int nT = (W >> 4) * (H >> 3);
    const int t = local % nT;
    const int rest = local / nT;
    const int coB = (rest % jb.nCoB) << 7;
    const int b = rest / jb.nCoB;

    const int tid = threadIdx.x, lane = tid & 31, wrp = tid >> 5;
    const int mw = wrp >> 1, nw = wrp & 1, gID = lane >> 2, tq = lane & 3;
    const int tilesX = W >> 4;
    const int x0 = (t % tilesX) << 4;
    const int y0 = (t / tilesX) << 3;
    const int HP = H + 2, WP = W + 2;

    const unsigned* inB = jb.src + (long)b * HP * WP * 128;

    float4 acc[2][8];
#pragma unroll
    for (int s = 0; s < 2; s++)
#pragma unroll
        for (int nt = 0; nt < 8; nt++) acc[s][nt] = make_float4(0.f, 0.f, 0.f, 0.f);

    auto stage = [&](int g, int buf) {
        unsigned* sIn = sm + buf * BUF_W;
        unsigned* sW  = sIn + SIN_W;
        for (int i = tid; i < 360; i += 256) {
            int pix = i >> 1, half = i & 1;
            int rw = pix / 18, cl = pix - rw * 18;
            const unsigned* src = inB + ((long)(y0 + rw) * WP + (x0 + cl)) * 128 + g * 8 + half * 4;
            cpa16(&sIn[pix * 8 + half * 4], src);
        }
        for (int i = tid; i < 2304; i += 256) {
            int half = i & 1;
            int n    = (i >> 1) & 127;
            int tap  = i >> 8;
            const unsigned* src = jb.wgt + (((long)(g * 9 + tap) * CoutPad) + coB + n) * 8 + half * 4;
            cpa16(&sW[(tap * 128 + n) * 8 + half * 4], src);
        }
        asm volatile("cp.async.commit_group;" ::: "memory");
    };

    stage(0, 0);
    stage(1, 1);

    for (int c = 0; c < 16; c++) {
        if (c < 15) asm volatile("cp.async.wait_group 1;" ::: "memory");
        else        asm volatile("cp.async.wait_group 0;" ::: "memory");
        __syncthreads();

        const unsigned* sIn = sm + (c & 1) * BUF_W;
        const unsigned* sW  = sIn + SIN_W;

#pragma unroll
        for (int tap = 0; tap < 9; tap++) {
            const int dy = tap / 3, dx = tap - 3 * (tap / 3);
            uint2 A0[2], A1[2];
#pragma unroll
            for (int s = 0; s < 2; s++) {
                const unsigned* p0 = sIn + ((2 * mw + s + dy) * 18 + gID + dx) * 8 + 2 * tq;
                A0[s] = *(const uint2*)p0;
                A1[s] = *(const uint2*)(p0 + 8 * 8);
            }
#pragma unroll
            for (int nt = 0; nt < 8; nt++) {
                uint2 Bv = *(const uint2*)(sW + ((tap * 128 + nw * 64 + nt * 8 + gID) * 8) + 2 * tq);
                mma16(acc[0][nt], A0[0], A1[0], Bv);
                mma16(acc[1][nt], A0[1], A1[1], Bv);
            }
        }
        __syncthreads();
        if (c + 2 < 16) stage(c + 2, c & 1);
    }

    // ---- epilogue ----
    if (!packed) {
        unsigned* ob = (unsigned*)jb.dst + (long)b * HP * WP * 128;
#pragma unroll
        for (int s = 0; s < 2; s++) {
            int y = y0 + 2 * mw + s;
            long rowb = (long)(y + 1) * WP * 128;
#pragma unroll
            for (int nt = 0; nt < 8; nt++) {
                int co = coB + nw * 64 + nt * 8 + (tq << 1);
                int p  = co >> 1;
                int wrd = (p >> 3) * 8 + slot_of(p & 7);
                float b0 = jb.bias[co], b1 = jb.bias[co + 1];
                float4 a = acc[s][nt];
                float v0 = a.x + b0, v1 = a.y + b1, v2 = a.z + b0, v3 = a.w + b1;
                if (relu) {
                    v0 = fmaxf(v0, 0.f); v1 = fmaxf(v1, 0.f);
                    v2 = fmaxf(v2, 0.f); v3 = fmaxf(v3, 0.f);
                }
                ob[rowb + (long)(x0 + gID + 1) * 128 + wrd] = pk(v0, v1);
                ob[rowb + (long)(x0 + gID + 9) * 128 + wrd] = pk(v2, v3);
            }
        }
    } else {
        float* out = (float*)jb.dst;
#pragma unroll
        for (int s = 0; s < 2; s++) {
            int y = y0 + 2 * mw + s;
            long base  = ((long)b * TOTLOC + jb.loc_off + (long)y * W + x0 + gID) * CHTOT + jb.ch_off;
            long base8 = base + 8L * CHTOT;
#pragma unroll
            for (int nt = 0; nt < 8; nt++) {
                int co = coB + nw * 64 + nt * 8 + (tq << 1);
                if (co < Cout) {
                    float bv = jb.bias[co];
                    float4 a = acc[s][nt];
                    out[base  + co] = a.x + bv;
                    out[base8 + co] = a.z + bv;
                    if (co + 1 < Cout) {
                        float bv1 = jb.bias[co + 1];
                        out[base  + co + 1] = a.y + bv1;
                        out[base8 + co + 1] = a.w + bv1;
                    }
                }
            }
        }
    }
}

// ---------------------------------------------------------------------------
// lateral 1x1 v2: 4 couts x 4 consecutive pixels per thread (float4 loads,
// 16 independent accumulator chains), NCHW fp32 -> padded NHWC bf16 words.
// ---------------------------------------------------------------------------
__global__ __launch_bounds__(256)
void lat_k(const float* __restrict__ in, const float* __restrict__ w,
           const float* __restrict__ bias, unsigned* __restrict__ out,
           int Cin, int H, int W)
{
    const int HW = H * W;
    const int nPx4 = HW >> 2;
    int idx = blockIdx.x * 256 + threadIdx.x;
    int total = B * 64 * nPx4;
    if (idx >= total) return;
    int px4 = idx % nPx4;
    int t   = idx / nPx4;
    int cg  = t % 64;
    int b   = t / 64;
    int co  = cg * 4;
    int px  = px4 * 4;

    float acc[4][4];
#pragma unroll
    for (int i = 0; i < 4; i++) {
        float bv = bias[co + i];
#pragma unroll
        for (int p = 0; p < 4; p++) acc[i][p] = bv;
    }

    const float* ip = in + (long)b * Cin * HW + px;
    const float* w0 = w + (long)(co + 0) * Cin;
    const float* w1 = w + (long)(co + 1) * Cin;
    const float* w2 = w + (long)(co + 2) * Cin;
    const float* w3 = w + (long)(co + 3) * Cin;

    for (int ci = 0; ci < Cin; ci++) {
        float4 v = *(const float4*)(ip + (long)ci * HW);
        float a = w0[ci], bq = w1[ci], cq = w2[ci], dq = w3[ci];
        acc[0][0] += a * v.x;  acc[0][1] += a * v.y;  acc[0][2] += a * v.z;  acc[0][3] += a * v.w;
        acc[1][0] += bq * v.x; acc[1][1] += bq * v.y; acc[1][2] += bq * v.z; acc[1][3] += bq * v.w;
        acc[2][0] += cq * v.x; acc[2][1] += cq * v.y; acc[2][2] += cq * v.z; acc[2][3] += cq * v.w;
        acc[3][0] += dq * v.x; acc[3][1] += dq * v.y; acc[3][2] += dq * v.z; acc[3][3] += dq * v.w;
    }

    const int y = px / W, xb = px % W;     // 4 consecutive x, same row (W % 4 == 0)
    const int p0 = 2 * cg, g = p0 >> 3;
    const int s0 = g * 8 + slot_of(p0 & 7), s1 = g * 8 + slot_of((p0 + 1) & 7);
    unsigned* rowp = out + ((long)(b * (H + 2) + y + 1) * (W + 2) + xb + 1) * 128;
#pragma unroll
    for (int p = 0; p < 4; p++) {
        unsigned* basep = rowp + (long)p * 128;
        basep[s0] = pk(acc[0][p], acc[1][p]);
        basep[s1] = pk(acc[2][p], acc[3][p]);
    }
}

// dst += nearest-up2(src), bf16x2 words, identical layouts
__global__ __launch_bounds__(256)
void upadd_k(unsigned* __restrict__ dst, const unsigned* __restrict__ src, int H, int W)
{
    long idx = (long)blockIdx.x * 256 + threadIdx.x;
    long total = (long)B * H * W * 128;
    if (idx >= total) return;
    int wrd = idx & 127;
    long p = idx >> 7;
    int x = p % W;
    int y = (p / W) % H;
    int b = p / ((long)W * H);
    unsigned* d = &dst[((long)(b * (H + 2) + y + 1) * (W + 2) + x + 1) * 128 + wrd];
    const unsigned* s = &src[((long)(b * (H / 2 + 2) + (y >> 1) + 1) * (W / 2 + 2) + (x >> 1) + 1) * 128 + wrd];
    __nv_bfloat162 dv = *(__nv_bfloat162*)d, sv = *(const __nv_bfloat162*)s;
    *d = pk(__bfloat162float(dv.x) + __bfloat162float(sv.x),
            __bfloat162float(dv.y) + __bfloat162float(sv.y));
}

__global__ void zero_k(float4* p, long n4)
{
    long i = (long)blockIdx.x * blockDim.x + threadIdx.x;
    long stride = (long)gridDim.x * blockDim.x;
    for (; i < n4; i += stride) p[i] = make_float4(0.f, 0.f, 0.f, 0.f);
}

// ---------------------------------------------------------------------------
// Fused, coalesced weight transform (R15). Block = (job j, cout co).
// ---------------------------------------------------------------------------
struct XJobs { const float* s[14]; const float* bb; const float* tb; };

__global__ __launch_bounds__(256)
void xform13_k(XJobs xj, unsigned* __restrict__ wt, unsigned* __restrict__ wt_cls,
               unsigned* __restrict__ wt_bc, float* __restrict__ bias_bc)
{
    __shared__ float w[2304];
    const int j = blockIdx.y;
    const int co = blockIdx.x;
    const int CoutPad = (j < 11) ? 256 : 128;
    if (co >= CoutPad) return;
    const int tid = threadIdx.x;

    unsigned* dst = (j < 11) ? (wt + (long)j * W256) : (j == 11 ? wt_cls : wt_bc);

    const float* srcRow = nullptr;
    if (j < 11)       srcRow = xj.s[j] + (long)co * 2304;
    else if (j == 11) { if (co < 80) srcRow = xj.s[11] + (long)co * 2304; }
    else {
        if (co < 4)       srcRow = xj.s[12] + (long)co * 2304;
        else if (co == 4) srcRow = xj.s[13];
        if (co == 0 && tid < 5)
            bias_bc[tid] = (tid < 4) ? xj.bb[tid] : xj.tb[0];
    }

    if (srcRow)
        for (int i = tid; i < 2304; i += 256) w[i] = srcRow[i];
    __syncthreads();

    if (tid < 144) {
        const int g = tid / 9, tap = tid - 9 * (tid / 9);
        unsigned wd[8];
        if (srcRow) {
#pragma unroll
            for (int v = 0; v < 8; v++) {
                int ci = 16 * g + 2 * v;
                wd[slot_of(v)] = pk(w[ci * 9 + tap], w[(ci + 1) * 9 + tap]);
            }
        } else {
#pragma unroll
            for (int v = 0; v < 8; v++) wd[v] = 0u;
        }
        unsigned* o = dst + (((long)(g * 9 + tap)) * CoutPad + co) * 8;
        *(uint4*)o       = make_uint4(wd[0], wd[1], wd[2], wd[3]);
        *(uint4*)(o + 4) = make_uint4(wd[4], wd[5], wd[6], wd[7]);
    }
}

// ---------------------------------------------------------------------------
extern "C" void kernel_launch(void* const* d_in, const int* in_sizes, int n_in,
                              void* d_out, int out_size)
{
    auto idxOf = [&](int sz, int ord) -> int {
        int c = 0;
        for (int i = 0; i < n_in; i++)
            if (in_sizes[i] == sz) { if (c == ord) return i; c++; }
        return -1;
    };
    const int i_c3  = idxOf(2 * 64 * 64 * 64, 0);
    const int i_c4  = idxOf(2 * 160 * 32 * 32, 0);
    const int i_c5  = idxOf(2 * 400 * 16 * 16, 0);
    const int i_l3w = idxOf(256 * 64, 0);
    const int i_l4w = idxOf(256 * 160, 0);
    const int i_l5w = idxOf(256 * 400, 0);
    const int i_o3w = idxOf(256 * 256 * 9, 0);
    const int i_o4w = idxOf(256 * 256 * 9, 1);
    const int i_o5w = idxOf(256 * 256 * 9, 2);
    const int i_scw = idxOf(4 * 256 * 256 * 9, 0);
    const int i_sbw = idxOf(4 * 256 * 256 * 9, 1);
    const int i_cw  = idxOf(80 * 256 * 9, 0);
    const int i_bw  = idxOf(4 * 256 * 9, 0);
    const int i_tw  = idxOf(1 * 256 * 9, 0);

    const float* c3 = (const float*)d_in[i_c3];
    const float* c4 = (const float*)d_in[i_c4];
    const float* c5 = (const float*)d_in[i_c5];
    const float* l3w = (const float*)d_in[i_l3w]; const float* l3b = (const float*)d_in[i_l3w + 1];
    const float* l4w = (const float*)d_in[i_l4w]; const float* l4b = (const float*)d_in[i_l4w + 1];
    const float* l5w = (const float*)d_in[i_l5w]; const float* l5b = (const float*)d_in[i_l5w + 1];
    const float* o3w = (const float*)d_in[i_o3w]; const float* o3b = (const float*)d_in[i_o3w + 1];
    const float* o4w = (const float*)d_in[i_o4w]; const float* o4b = (const float*)d_in[i_o4w + 1];
    const float* o5w = (const float*)d_in[i_o5w]; const float* o5b = (const float*)d_in[i_o5w + 1];
    const float* scw = (const float*)d_in[i_scw]; const float* scb = (const float*)d_in[i_scw + 1];
    const float* sbw = (const float*)d_in[i_sbw]; const float* sbb = (const float*)d_in[i_sbw + 1];
    const float* cw  = (const float*)d_in[i_cw];  const float* cb  = (const float*)d_in[i_cw + 1];
    const float* bw  = (const float*)d_in[i_bw];  const float* bb  = (const float*)d_in[i_bw + 1];
    const float* tw  = (const float*)d_in[i_tw];  const float* tb  = (const float*)d_in[i_tw + 1];

    unsigned *act, *wt, *wt_cls, *wt_bc;
    float* bias_bc;
    cudaGetSymbolAddress((void**)&act, g_act);
    cudaGetSymbolAddress((void**)&wt, g_wt);
    cudaGetSymbolAddress((void**)&wt_cls, g_wt_cls);
    cudaGetSymbolAddress((void**)&wt_bc, g_wt_bc);
    cudaGetSymbolAddress((void**)&bias_bc, g_bias_bc);

    // buffer carve per level: 0=lat, 1=p, 2=tA, 3=tB, 4=tC, 5=tD
    unsigned* L3p[6]; unsigned* L4p[6]; unsigned* L5p[6];
    for (int i = 0; i < 6; i++) L3p[i] = act + (long)i * S3W;
    unsigned* b4 = act + 6L * S3W;
    for (int i = 0; i < 6; i++) L4p[i] = b4 + (long)i * S4W;
    unsigned* b5 = b4 + 6L * S4W;
    for (int i = 0; i < 6; i++) L5p[i] = b5 + (long)i * S5W;

    cudaFuncSetAttribute(conv_tc_k, cudaFuncAttributeMaxDynamicSharedMemorySize, SMEM_BYTES);

    float* out = (float*)d_out;

    // launch 0: zero activation pool (borders must stay 0)
    zero_k<<<512, 256>>>((float4*)act, (long)(6L * S3W + 6L * S4W + 6L * S5W) / 4);

    // launch 1: all weight transforms + bias_bc, fused & coalesced
    {
        XJobs xj;
        xj.s[0] = o3w; xj.s[1] = o4w; xj.s[2] = o5w;
        for (int i = 0; i < 4; i++) {
            xj.s[3 + i] = scw + (long)i * 256 * 256 * 9;
            xj.s[7 + i] = sbw + (long)i * 256 * 256 * 9;
        }
        xj.s[11] = cw; xj.s[12] = bw; xj.s[13] = tw;
        xj.bb = bb; xj.tb = tb;
        xform13_k<<<dim3(256, 13), 256>>>(xj, wt, wt_cls, wt_bc, bias_bc);
    }

    // launches 2-4: FPN laterals (4 pixels per thread)
    lat_k<<<(B * 64 * 64 + 255) / 256, 256>>>(c5, l5w, l5b, L5p[0], 400, 16, 16);
    lat_k<<<(B * 64 * 256 + 255) / 256, 256>>>(c4, l4w, l4b, L4p[0], 160, 32, 32);
    lat_k<<<(B * 64 * 1024 + 255) / 256, 256>>>(c3, l3w, l3b, L3p[0], 64, 64, 64);

    const int nT[3] = { 32, 8, 2 };
    const int Hs[3] = { 64, 32, 16 }, Ws[3] = { 64, 32, 16 };
    const int locs[3] = { 0, 4096, 5120 };

    auto mkJob = [&](const unsigned* src, const unsigned* w, const float* bias,
                     void* dst, int L, int start, int nCoB, int Cout, int flags,
                     int loc, int ch) {
        Job j;
        j.src = src; j.wgt = w; j.bias = bias; j.dst = dst;
        j.H = Hs[L]; j.W = Ws[L]; j.start = start; j.nCoB = nCoB;
        j.Cout = Cout; j.flags = flags; j.loc_off = loc; j.ch_off = ch;
        return j;
    };

    // ---- FPN: up-adds first (they only read laterals), then all three
    //      out-convs fused into ONE launch (168 CTAs, independent) ----
    {
        long n = (long)B * 32 * 32 * 128;
        upadd_k<<<(int)((n + 255) / 256), 256>>>(L4p[0], L5p[0], 32, 32);
        n = (long)B * 64 * 64 * 128;
        upadd_k<<<(int)((n + 255) / 256), 256>>>(L3p[0], L4p[0], 64, 64);

        JobSet js; js.nj = 3;
        int start = 0;
        js.j[0] = mkJob(L3p[0], wt + 0L * W256, o3b, L3p[1], 0, start, 2, 256, 0, 0, 0);
        start += nT[0] * 4;
        js.j[1] = mkJob(L4p[0], wt + 1L * W256, o4b, L4p[1], 1, start, 2, 256, 0, 0, 0);
        start += nT[1] * 4;
        js.j[2] = mkJob(L5p[0], wt + 2L * W256, o5b, L5p[1], 2, start, 2, 256, 0, 0, 0);
        start += nT[2] * 4;
        conv_tc_k<<<start, 256, SMEM_BYTES>>>(js);
    }

    // ---- fused stems: 4 launches, each = 3 levels x 2 branches (336 CTAs) ----
    unsigned** Lp[3] = { L3p, L4p, L5p };
    for (int i = 0; i < 4; i++) {
        int sc_s = (i == 0) ? 1 : ((i & 1) ? 2 : 3);
        int sc_d = (i & 1) ? 3 : 2;
        int sb_s = (i == 0) ? 1 : ((i & 1) ? 4 : 5);
        int sb_d = (i & 1) ? 5 : 4;
        JobSet js; js.nj = 6;
        int start = 0;
        for (int L = 0; L < 3; L++) {
            js.j[2 * L] = mkJob(Lp[L][sc_s], wt + (3 + i) * (long)W256, scb + i * 256,
                                Lp[L][sc_d], L, start, 2, 256, 1, 0, 0);
            start += nT[L] * 4;
            js.j[2 * L + 1] = mkJob(Lp[L][sb_s], wt + (7 + i) * (long)W256, sbb + i * 256,
                                    Lp[L][sb_d], L, start, 2, 256, 1, 0, 0);
            start += nT[L] * 4;
        }
        conv_tc_k<<<start, 256, SMEM_BYTES>>>(js);
    }

    // ---- fused finals: cls (from tB=3) + box/ctr (from tD=5), 168 CTAs ----
    {
        JobSet js; js.nj = 6;
        int start = 0;
        for (int L = 0; L < 3; L++) {
            js.j[L] = mkJob(Lp[L][3], wt_cls, cb, out, L, start, 1, NUMC, 2, locs[L], 0);
            start += nT[L] * 2;
        }
        for (int L = 0; L < 3; L++) {
            js.j[3 + L] = mkJob(Lp[L][5], wt_bc, bias_bc, out, L, start, 1, 5, 2, locs[L], 80);
            start += nT[L] * 2;
        }
        conv_tc_k<<<start, 256, SMEM_BYTES>>>(js);
    }
    (void)out_size;
}

// round 17
// speedup vs baseline: 10.3365x; 1.1373x over previous
#include <cuda_runtime.h>
#include <cuda_bf16.h>
#include <cstdint>

// ---------------------------------------------------------------------------
// FCOS head on GB300 — round 17: R16 + fused single-launch laterals with
// explicit MLP=4 (manual ci-by-4 unroll, batched float4 loads).
// ---------------------------------------------------------------------------

#define NUMC 80
#define CHTOT 85
#define TOTLOC 5376
#define B 2

// ---- activation pool: padded NHWC bf16x2 words, slot-permuted, 6 bufs/level
#define S3W (2 * 66 * 66 * 128)
#define S4W (2 * 34 * 34 * 128)
#define S5W (2 * 18 * 18 * 128)
__device__ unsigned g_act[6 * S3W + 6 * S4W + 6 * S5W];

// ---- transformed bf16 weights: [group16][tap9][coutPad][8 words], permuted
#define W256 (16 * 9 * 256 * 8)
#define W128 (16 * 9 * 128 * 8)
__device__ __align__(16) unsigned g_wt[11 * W256];   // out3/4/5, stem_cls0-3, stem_box0-3
__device__ __align__(16) unsigned g_wt_cls[W128];    // cls, pad 128
__device__ __align__(16) unsigned g_wt_bc [W128];    // box(4)+ctr(1), pad 128
__device__ float g_bias_bc[5];

__device__ __forceinline__ unsigned pk(float a, float b) {
    __nv_bfloat162 h = __floats2bfloat162_rn(a, b);
    return *(unsigned*)&h;
}
__device__ __forceinline__ int slot_of(int w) { return ((w & 3) << 1) | (w >> 2); }

__device__ __forceinline__ void cpa16(void* smem, const void* g) {
    unsigned s = (unsigned)__cvta_generic_to_shared(smem);
    asm volatile("cp.async.cg.shared.global [%0], [%1], 16;" :: "r"(s), "l"(g) : "memory");
}

__device__ __forceinline__ void mma16(float4& d, uint2 A0, uint2 A1, uint2 Bv) {
    asm volatile(
        "mma.sync.aligned.m16n8k16.row.col.f32.bf16.bf16.f32 "
        "{%0,%1,%2,%3}, {%4,%5,%6,%7}, {%8,%9}, {%0,%1,%2,%3};\n"
        : "+f"(d.x), "+f"(d.y), "+f"(d.z), "+f"(d.w)
        : "r"(A0.x), "r"(A1.x), "r"(A0.y), "r"(A1.y),
          "r"(Bv.x), "r"(Bv.y));
}

// ---------------------------------------------------------------------------
// bf16 tensor-core 3x3 conv, multi-job dispatch, 8-word smem stride.
// CTA: 128 pixels (8r x 16c) x 128 couts; 8 warps = 4m x 2n; 16 K-chunks of
// 16 cin, cp.async double-buffered.  flags: 1=relu, 2=packed output.
// ---------------------------------------------------------------------------
#define SIN_W (180 * 8)
#define SW_W  (9 * 128 * 8)
#define BUF_W (SIN_W + SW_W)
#define SMEM_BYTES (2 * BUF_W * 4)       // 85,248 bytes -> 2 CTAs/SM

struct Job {
    const unsigned* src;
    const unsigned* wgt;
    const float* bias;
    void* dst;
    int H, W, start, nCoB, Cout, flags, loc_off, ch_off;
};
struct JobSet { Job j[6]; int nj; };

__global__ __launch_bounds__(256, 2)
void conv_tc_k(JobSet js)
{
    extern __shared__ unsigned sm[];

    int ji = 0;
    for (int k = 1; k < js.nj; k++)
        if ((int)blockIdx.x >= js.j[k].start) ji = k;
    const Job jb = js.j[ji];
    const int H = jb.H, W = jb.W;
    const int Cout = jb.Cout, CoutPad = jb.nCoB << 7;
    const int relu = jb.flags & 1, packed = jb.flags & 2;

    const int local = blockIdx.x - jb.start;
    const int nT = (W >> 4) * (H >> 3);
    const int t = local % nT;
    const int rest = local / nT;
    const int coB = (rest % jb.nCoB) << 7;
    const int b = rest / jb.nCoB;

    const int tid = threadIdx.x, lane = tid & 31, wrp = tid >> 5;
    const int mw = wrp >> 1, nw = wrp & 1, gID = lane >> 2, tq = lane & 3;
    const int tilesX = W >> 4;
    const int x0 = (t % tilesX) << 4;
    const int y0 = (t / tilesX) << 3;
    const int HP = H + 2, WP = W + 2;

    const unsigned* inB = jb.src + (long)b * HP * WP * 128;

    float4 acc[2][8];
#pragma unroll
    for (int s = 0; s < 2; s++)
#pragma unroll
        for (int nt = 0; nt < 8; nt++) acc[s][nt] = make_float4(0.f, 0.f, 0.f, 0.f);

    auto stage = [&](int g, int buf) {
        unsigned* sIn = sm + buf * BUF_W;
        unsigned* sW  = sIn + SIN_W;
        for (int i = tid; i < 360; i += 256) {
            int pix = i >> 1, half = i & 1;
            int rw = pix / 18, cl = pix - rw * 18;
            const unsigned* src = inB + ((long)(y0 + rw) * WP + (x0 + cl)) * 128 + g * 8 + half * 4;
            cpa16(&sIn[pix * 8 + half * 4], src);
        }
        for (int i = tid; i < 2304; i += 256) {
            int half = i & 1;
            int n    = (i >> 1) & 127;
            int tap  = i >> 8;
            const unsigned* src = jb.wgt + (((long)(g * 9 + tap) * CoutPad) + coB + n) * 8 + half * 4;
            cpa16(&sW[(tap * 128 + n) * 8 + half * 4], src);
        }
        asm volatile("cp.async.commit_group;" ::: "memory");
    };

    stage(0, 0);
    stage(1, 1);

    for (int c = 0; c < 16; c++) {
        if (c < 15) asm volatile("cp.async.wait_group 1;" ::: "memory");
        else        asm volatile("cp.async.wait_group 0;" ::: "memory");
        __syncthreads();

        const unsigned* sIn = sm + (c & 1) * BUF_W;
        const unsigned* sW  = sIn + SIN_W;

#pragma unroll
        for (int tap = 0; tap < 9; tap++) {
            const int dy = tap / 3, dx = tap - 3 * (tap / 3);
            uint2 A0[2], A1[2];
#pragma unroll
            for (int s = 0; s < 2; s++) {
                const unsigned* p0 = sIn + ((2 * mw + s + dy) * 18 + gID + dx) * 8 + 2 * tq;
                A0[s] = *(const uint2*)p0;
                A1[s] = *(const uint2*)(p0 + 8 * 8);
            }
#pragma unroll
            for (int nt = 0; nt < 8; nt++) {
                uint2 Bv = *(const uint2*)(sW + ((tap * 128 + nw * 64 + nt * 8 + gID) * 8) + 2 * tq);
                mma16(acc[0][nt], A0[0], A1[0], Bv);
                mma16(acc[1][nt], A0[1], A1[1], Bv);
            }
        }
        __syncthreads();
        if (c + 2 < 16) stage(c + 2, c & 1);
    }

    // ---- epilogue ----
    if (!packed) {
        unsigned* ob = (unsigned*)jb.dst + (long)b * HP * WP * 128;
#pragma unroll
        for (int s = 0; s < 2; s++) {
            int y = y0 + 2 * mw + s;
            long rowb = (long)(y + 1) * WP * 128;
#pragma unroll
            for (int nt = 0; nt < 8; nt++) {
                int co = coB + nw * 64 + nt * 8 + (tq << 1);
                int p  = co >> 1;
                int wrd = (p >> 3) * 8 + slot_of(p & 7);
                float b0 = jb.bias[co], b1 = jb.bias[co + 1];
                float4 a = acc[s][nt];
                float v0 = a.x + b0, v1 = a.y + b1, v2 = a.z + b0, v3 = a.w + b1;
                if (relu) {
                    v0 = fmaxf(v0, 0.f); v1 = fmaxf(v1, 0.f);
                    v2 = fmaxf(v2, 0.f); v3 = fmaxf(v3, 0.f);
                }
                ob[rowb + (long)(x0 + gID + 1) * 128 + wrd] = pk(v0, v1);
                ob[rowb + (long)(x0 + gID + 9) * 128 + wrd] = pk(v2, v3);
            }
        }
    } else {
        float* out = (float*)jb.dst;
#pragma unroll
        for (int s = 0; s < 2; s++) {
            int y = y0 + 2 * mw + s;
            long base  = ((long)b * TOTLOC + jb.loc_off + (long)y * W + x0 + gID) * CHTOT + jb.ch_off;
            long base8 = base + 8L * CHTOT;
#pragma unroll
            for (int nt = 0; nt < 8; nt++) {
                int co = coB + nw * 64 + nt * 8 + (tq << 1);
                if (co < Cout) {
                    float bv = jb.bias[co];
                    float4 a = acc[s][nt];
                    out[base  + co] = a.x + bv;
                    out[base8 + co] = a.z + bv;
                    if (co + 1 < Cout) {
                        float bv1 = jb.bias[co + 1];
                        out[base  + co + 1] = a.y + bv1;
                        out[base8 + co + 1] = a.w + bv1;
                    }
                }
            }
        }
    }
}

// ---------------------------------------------------------------------------
// Fused laterals: all three 1x1 convs in ONE launch. 4 couts x 4 consecutive
// pixels per thread; ci loop stepped by 4 with all 4 float4 loads batched
// (MLP=4). fp32 accumulate in ascending ci (same order as before).
// ---------------------------------------------------------------------------
struct LatJob {
    const float* in; const float* w; const float* bias;
    unsigned* out; int Cin, H, W, start;
};
struct LatSet { LatJob j[3]; };

__global__ __launch_bounds__(256)
void lat3_k(LatSet ls)
{
    int ji = 0;
    if ((int)blockIdx.x >= ls.j[1].start) ji = 1;
    if ((int)blockIdx.x >= ls.j[2].start) ji = 2;
    const LatJob jb = ls.j[ji];
    const int H = jb.H, W = jb.W, Cin = jb.Cin;
    const int HW = H * W;
    const int nPx4 = HW >> 2;

    int idx = (blockIdx.x - jb.start) * 256 + threadIdx.x;
    if (idx >= B * 64 * nPx4) return;
    int px4 = idx % nPx4;
    int t   = idx / nPx4;
    int cg  = t % 64;
    int b   = t / 64;
    int co  = cg * 4;
    int px  = px4 * 4;

    float acc[4][4];
#pragma unroll
    for (int i = 0; i < 4; i++) {
        float bv = jb.bias[co + i];
#pragma unroll
        for (int p = 0; p < 4; p++) acc[i][p] = bv;
    }

    const float* ip = jb.in + (long)b * Cin * HW + px;
    const float* w0 = jb.w + (long)(co + 0) * Cin;
    const float* w1 = jb.w + (long)(co + 1) * Cin;
    const float* w2 = jb.w + (long)(co + 2) * Cin;
    const float* w3 = jb.w + (long)(co + 3) * Cin;

    for (int ci = 0; ci < Cin; ci += 4) {
        // batch 4 independent activation loads first (MLP=4)
        float4 v[4];
        v[0] = *(const float4*)(ip + (long)(ci + 0) * HW);
        v[1] = *(const float4*)(ip + (long)(ci + 1) * HW);
        v[2] = *(const float4*)(ip + (long)(ci + 2) * HW);
        v[3] = *(const float4*)(ip + (long)(ci + 3) * HW);
#pragma unroll
        for (int k = 0; k < 4; k++) {
            float a = w0[ci + k], bq = w1[ci + k], cq = w2[ci + k], dq = w3[ci + k];
            acc[0][0] += a * v[k].x;  acc[0][1] += a * v[k].y;  acc[0][2] += a * v[k].z;  acc[0][3] += a * v[k].w;
            acc[1][0] += bq * v[k].x; acc[1][1] += bq * v[k].y; acc[1][2] += bq * v[k].z; acc[1][3] += bq * v[k].w;
            acc[2][0] += cq * v[k].x; acc[2][1] += cq * v[k].y; acc[2][2] += cq * v[k].z; acc[2][3] += cq * v[k].w;
            acc[3][0] += dq * v[k].x; acc[3][1] += dq * v[k].y; acc[3][2] += dq * v[k].z; acc[3][3] += dq * v[k].w;
        }
    }

    const int y = px / W, xb = px % W;     // 4 consecutive x, same row (W % 4 == 0)
    const int p0 = 2 * cg, g = p0 >> 3;
    const int s0 = g * 8 + slot_of(p0 & 7), s1 = g * 8 + slot_of((p0 + 1) & 7);
    unsigned* rowp = jb.out + ((long)(b * (H + 2) + y + 1) * (W + 2) + xb + 1) * 128;
#pragma unroll
    for (int p = 0; p < 4; p++) {
        unsigned* basep = rowp + (long)p * 128;
        basep[s0] = pk(acc[0][p], acc[1][p]);
        basep[s1] = pk(acc[2][p], acc[3][p]);
    }
}

// dst += nearest-up2(src), bf16x2 words, identical layouts
__global__ __launch_bounds__(256)
void upadd_k(unsigned* __restrict__ dst, const unsigned* __restrict__ src, int H, int W)
{
    long idx = (long)blockIdx.x * 256 + threadIdx.x;
    long total = (long)B * H * W * 128;
    if (idx >= total) return;
    int wrd = idx & 127;
    long p = idx >> 7;
    int x = p % W;
    int y = (p / W) % H;
    int b = p / ((long)W * H);
    unsigned* d = &dst[((long)(b * (H + 2) + y + 1) * (W + 2) + x + 1) * 128 + wrd];
    const unsigned* s = &src[((long)(b * (H / 2 + 2) + (y >> 1) + 1) * (W / 2 + 2) + (x >> 1) + 1) * 128 + wrd];
    __nv_bfloat162 dv = *(__nv_bfloat162*)d, sv = *(const __nv_bfloat162*)s;
    *d = pk(__bfloat162float(dv.x) + __bfloat162float(sv.x),
            __bfloat162float(dv.y) + __bfloat162float(sv.y));
}

__global__ void zero_k(float4* p, long n4)
{
    long i = (long)blockIdx.x * blockDim.x + threadIdx.x;
    long stride = (long)gridDim.x * blockDim.x;
    for (; i < n4; i += stride) p[i] = make_float4(0.f, 0.f, 0.f, 0.f);
}

// ---------------------------------------------------------------------------
// Fused, coalesced weight transform. Block = (job j, cout co).
// ---------------------------------------------------------------------------
struct XJobs { const float* s[14]; const float* bb; const float* tb; };

__global__ __launch_bounds__(256)
void xform13_k(XJobs xj, unsigned* __restrict__ wt, unsigned* __restrict__ wt_cls,
               unsigned* __restrict__ wt_bc, float* __restrict__ bias_bc)
{
    __shared__ float w[2304];
    const int j = blockIdx.y;
    const int co = blockIdx.x;
    const int CoutPad = (j < 11) ? 256 : 128;
    if (co >= CoutPad) return;
    const int tid = threadIdx.x;

    unsigned* dst = (j < 11) ? (wt + (long)j * W256) : (j == 11 ? wt_cls : wt_bc);

    const float* srcRow = nullptr;
    if (j < 11)       srcRow = xj.s[j] + (long)co * 2304;
    else if (j == 11) { if (co < 80) srcRow = xj.s[11] + (long)co * 2304; }
    else {
        if (co < 4)       srcRow = xj.s[12] + (long)co * 2304;
        else if (co == 4) srcRow = xj.s[13];
        if (co == 0 && tid < 5)
            bias_bc[tid] = (tid < 4) ? xj.bb[tid] : xj.tb[0];
    }

    if (srcRow)
        for (int i = tid; i < 2304; i += 256) w[i] = srcRow[i];
    __syncthreads();

    if (tid < 144) {
        const int g = tid / 9, tap = tid - 9 * (tid / 9);
        unsigned wd[8];
        if (srcRow) {
#pragma unroll
            for (int v = 0; v < 8; v++) {
                int ci = 16 * g + 2 * v;
                wd[slot_of(v)] = pk(w[ci * 9 + tap], w[(ci + 1) * 9 + tap]);
            }
        } else {
#pragma unroll
            for (int v = 0; v < 8; v++) wd[v] = 0u;
        }
        unsigned* o = dst + (((long)(g * 9 + tap)) * CoutPad + co) * 8;
        *(uint4*)o       = make_uint4(wd[0], wd[1], wd[2], wd[3]);
        *(uint4*)(o + 4) = make_uint4(wd[4], wd[5], wd[6], wd[7]);
    }
}

// ---------------------------------------------------------------------------
extern "C" void kernel_launch(void* const* d_in, const int* in_sizes, int n_in,
                              void* d_out, int out_size)
{
    auto idxOf = [&](int sz, int ord) -> int {
        int c = 0;
        for (int i = 0; i < n_in; i++)
            if (in_sizes[i] == sz) { if (c == ord) return i; c++; }
        return -1;
    };
    const int i_c3  = idxOf(2 * 64 * 64 * 64, 0);
    const int i_c4  = idxOf(2 * 160 * 32 * 32, 0);
    const int i_c5  = idxOf(2 * 400 * 16 * 16, 0);
    const int i_l3w = idxOf(256 * 64, 0);
    const int i_l4w = idxOf(256 * 160, 0);
    const int i_l5w = idxOf(256 * 400, 0);
    const int i_o3w = idxOf(256 * 256 * 9, 0);
    const int i_o4w = idxOf(256 * 256 * 9, 1);
    const int i_o5w = idxOf(256 * 256 * 9, 2);
    const int i_scw = idxOf(4 * 256 * 256 * 9, 0);
    const int i_sbw = idxOf(4 * 256 * 256 * 9, 1);
    const int i_cw  = idxOf(80 * 256 * 9, 0);
    const int i_bw  = idxOf(4 * 256 * 9, 0);
    const int i_tw  = idxOf(1 * 256 * 9, 0);

    const float* c3 = (const float*)d_in[i_c3];
    const float* c4 = (const float*)d_in[i_c4];
    const float* c5 = (const float*)d_in[i_c5];
    const float* l3w = (const float*)d_in[i_l3w]; const float* l3b = (const float*)d_in[i_l3w + 1];
    const float* l4w = (const float*)d_in[i_l4w]; const float* l4b = (const float*)d_in[i_l4w + 1];
    const float* l5w = (const float*)d_in[i_l5w]; const float* l5b = (const float*)d_in[i_l5w + 1];
    const float* o3w = (const float*)d_in[i_o3w]; const float* o3b = (const float*)d_in[i_o3w + 1];
    const float* o4w = (const float*)d_in[i_o4w]; const float* o4b = (const float*)d_in[i_o4w + 1];
    const float* o5w = (const float*)d_in[i_o5w]; const float* o5b = (const float*)d_in[i_o5w + 1];
    const float* scw = (const float*)d_in[i_scw]; const float* scb = (const float*)d_in[i_scw + 1];
    const float* sbw = (const float*)d_in[i_sbw]; const float* sbb = (const float*)d_in[i_sbw + 1];
    const float* cw  = (const float*)d_in[i_cw];  const float* cb  = (const float*)d_in[i_cw + 1];
    const float* bw  = (const float*)d_in[i_bw];  const float* bb  = (const float*)d_in[i_bw + 1];
    const float* tw  = (const float*)d_in[i_tw];  const float* tb  = (const float*)d_in[i_tw + 1];

    unsigned *act, *wt, *wt_cls, *wt_bc;
    float* bias_bc;
    cudaGetSymbolAddress((void**)&act, g_act);
    cudaGetSymbolAddress((void**)&wt, g_wt);
    cudaGetSymbolAddress((void**)&wt_cls, g_wt_cls);
    cudaGetSymbolAddress((void**)&wt_bc, g_wt_bc);
    cudaGetSymbolAddress((void**)&bias_bc, g_bias_bc);

    // buffer carve per level: 0=lat, 1=p, 2=tA, 3=tB, 4=tC, 5=tD
    unsigned* L3p[6]; unsigned* L4p[6]; unsigned* L5p[6];
    for (int i = 0; i < 6; i++) L3p[i] = act + (long)i * S3W;
    unsigned* b4 = act + 6L * S3W;
    for (int i = 0; i < 6; i++) L4p[i] = b4 + (long)i * S4W;
    unsigned* b5 = b4 + 6L * S4W;
    for (int i = 0; i < 6; i++) L5p[i] = b5 + (long)i * S5W;

    cudaFuncSetAttribute(conv_tc_k, cudaFuncAttributeMaxDynamicSharedMemorySize, SMEM_BYTES);

    float* out = (float*)d_out;

    // launch 0: zero activation pool (borders must stay 0)
    zero_k<<<512, 256>>>((float4*)act, (long)(6L * S3W + 6L * S4W + 6L * S5W) / 4);

    // launch 1: all weight transforms + bias_bc, fused & coalesced
    {
        XJobs xj;
        xj.s[0] = o3w; xj.s[1] = o4w; xj.s[2] = o5w;
        for (int i = 0; i < 4; i++) {
            xj.s[3 + i] = scw + (long)i * 256 * 256 * 9;
            xj.s[7 + i] = sbw + (long)i * 256 * 256 * 9;
        }
        xj.s[11] = cw; xj.s[12] = bw; xj.s[13] = tw;
        xj.bb = bb; xj.tb = tb;
        xform13_k<<<dim3(256, 13), 256>>>(xj, wt, wt_cls, wt_bc, bias_bc);
    }

    // launch 2: ALL THREE laterals fused (672 CTAs)
    {
        LatSet ls;
        int start = 0;
        // c3: 64x64, nPx4=1024 -> 512 blocks
        ls.j[0] = LatJob{ c3, l3w, l3b, L3p[0], 64, 64, 64, start };
        start += (B * 64 * 1024) / 256;
        // c4: 32x32, nPx4=256 -> 128 blocks
        ls.j[1] = LatJob{ c4, l4w, l4b, L4p[0], 160, 32, 32, start };
        start += (B * 64 * 256) / 256;
        // c5: 16x16, nPx4=64 -> 32 blocks
        ls.j[2] = LatJob{ c5, l5w, l5b, L5p[0], 400, 16, 16, start };
        start += (B * 64 * 64) / 256;
        lat3_k<<<start, 256>>>(ls);
    }

    const int nT[3] = { 32, 8, 2 };
    const int Hs[3] = { 64, 32, 16 }, Ws[3] = { 64, 32, 16 };
    const int locs[3] = { 0, 4096, 5120 };

    auto mkJob = [&](const unsigned* src, const unsigned* w, const float* bias,
                     void* dst, int L, int start, int nCoB, int Cout, int flags,
                     int loc, int ch) {
        Job j;
        j.src = src; j.wgt = w; j.bias = bias; j.dst = dst;
        j.H = Hs[L]; j.W = Ws[L]; j.start = start; j.nCoB = nCoB;
        j.Cout = Cout; j.flags = flags; j.loc_off = loc; j.ch_off = ch;
        return j;
    };

    // ---- FPN: up-adds first (they only read laterals), then all three
    //      out-convs fused into ONE launch (168 CTAs, independent) ----
    {
        long n = (long)B * 32 * 32 * 128;
        upadd_k<<<(int)((n + 255) / 256), 256>>>(L4p[0], L5p[0], 32, 32);
        n = (long)B * 64 * 64 * 128;
        upadd_k<<<(int)((n + 255) / 256), 256>>>(L3p[0], L4p[0], 64, 64);

        JobSet js; js.nj = 3;
        int start = 0;
        js.j[0] = mkJob(L3p[0], wt + 0L * W256, o3b, L3p[1], 0, start, 2, 256, 0, 0, 0);
        start += nT[0] * 4;
        js.j[1] = mkJob(L4p[0], wt + 1L * W256, o4b, L4p[1], 1, start, 2, 256, 0, 0, 0);
        start += nT[1] * 4;
        js.j[2] = mkJob(L5p[0], wt + 2L * W256, o5b, L5p[1], 2, start, 2, 256, 0, 0, 0);
        start += nT[2] * 4;
        conv_tc_k<<<start, 256, SMEM_BYTES>>>(js);
    }

    // ---- fused stems: 4 launches, each = 3 levels x 2 branches (336 CTAs) ----
    unsigned** Lp[3] = { L3p, L4p, L5p };
    for (int i = 0; i < 4; i++) {
        int sc_s = (i == 0) ? 1 : ((i & 1) ? 2 : 3);
        int sc_d = (i & 1) ? 3 : 2;
        int sb_s = (i == 0) ? 1 : ((i & 1) ? 4 : 5);
        int sb_d = (i & 1) ? 5 : 4;
        JobSet js; js.nj = 6;
        int start = 0;
        for (int L = 0; L < 3; L++) {
            js.j[2 * L] = mkJob(Lp[L][sc_s], wt + (3 + i) * (long)W256, scb + i * 256,
                                Lp[L][sc_d], L, start, 2, 256, 1, 0, 0);
            start += nT[L] * 4;
            js.j[2 * L + 1] = mkJob(Lp[L][sb_s], wt + (7 + i) * (long)W256, sbb + i * 256,
                                    Lp[L][sb_d], L, start, 2, 256, 1, 0, 0);
            start += nT[L] * 4;
        }
        conv_tc_k<<<start, 256, SMEM_BYTES>>>(js);
    }

    // ---- fused finals: cls (from tB=3) + box/ctr (from tD=5), 168 CTAs ----
    {
        JobSet js; js.nj = 6;
        int start = 0;
        for (int L = 0; L < 3; L++) {
            js.j[L] = mkJob(Lp[L][3], wt_cls, cb, out, L, start, 1, NUMC, 2, locs[L], 0);
            start += nT[L] * 2;
        }
        for (int L = 0; L < 3; L++) {
            js.j[3 + L] = mkJob(Lp[L][5], wt_bc, bias_bc, out, L, start, 1, 5, 2, locs[L], 80);
            start += nT[L] * 2;
        }
        conv_tc_k<<<start, 256, SMEM_BYTES>>>(js);
    }
    (void)out_size;
}